// round 7
// baseline (speedup 1.0000x reference)
#include <cuda_runtime.h>
#include <math.h>
#include <stdint.h>

#define NN 8000
#define EE 24000
#define BB 256
#define ATOMD 133
#define BONDD 14
#define HD 256
#define NHEADS 8
#define HHD 2048
#define NLAYERS 5
#define MAXD 64

#define MBLK 504                 // ceil(8064/16) m-fragment blocks
#define WELEM (HD * HHD)         // 524288 floats per weight matrix

// ---------------- scratch (device globals; no allocation allowed) -------------
__device__ float g_h[NN * HD];
__device__ float g_xl[NN * HHD];
__device__ float g_xr[NN * HHD];
__device__ float g_deg[NN];
__device__ float g_loopsum[NN * BONDD];
__device__ float g_loop[NN * BONDD];
__device__ float g_gate[NN];
__device__ float g_ge[NN];
__device__ unsigned g_gm[BB];
__device__ float g_gs[BB];
// CSR by destination
__device__ int g_degi[NN];
__device__ int g_csroff[NN + 1];
__device__ int g_cur[NN];
__device__ int g_csre[EE];
// tf32-rounded, mma-fragment-major copies
__device__ float g_hf[MBLK * 32 * 128];     // A fragments
__device__ float g_Wf[10 * WELEM];          // B fragments

__device__ __forceinline__ unsigned fenc(float f) {
    unsigned u = __float_as_uint(f);
    return (u & 0x80000000u) ? ~u : (u | 0x80000000u);
}
__device__ __forceinline__ float fdec(unsigned u) {
    u = (u & 0x80000000u) ? (u & 0x7FFFFFFFu) : ~u;
    return __uint_as_float(u);
}
#define ENC_NEG_INF 0x007FFFFFu

__device__ __forceinline__ float tf32r(float f) {
    uint32_t u;
    asm("cvt.rna.tf32.f32 %0, %1;" : "=r"(u) : "f"(f));
    return __uint_as_float(u);
}

// A-fragment store: element (m, k) of h -> fragment-major global layout.
__device__ __forceinline__ void store_frag_h(int m, int k, float v) {
    int blk = (m >> 4) * 32 + (k >> 3);
    int lane = (m & 7) * 4 + (k & 3);
    int slot = ((m >> 3) & 1) | (((k >> 2) & 1) << 1);
    g_hf[blk * 128 + lane * 4 + slot] = tf32r(v);
}

#define CP16(dst, src) \
    asm volatile("cp.async.cg.shared.global [%0], [%1], 16;" \
                 :: "r"(dst), "l"(src) : "memory")

__device__ __forceinline__ uint32_t smem_u32(const void* p) {
    uint32_t a;
    asm("{ .reg .u64 t; cvta.to.shared.u64 t, %1; cvt.u32.u64 %0, t; }"
        : "=r"(a) : "l"(p));
    return a;
}

__device__ __forceinline__ void mma_tf32(float* c, const uint4& a, const uint2& b) {
    asm volatile(
        "mma.sync.aligned.m16n8k8.row.col.f32.tf32.tf32.f32 "
        "{%0,%1,%2,%3}, {%4,%5,%6,%7}, {%8,%9}, {%0,%1,%2,%3};\n"
        : "+f"(c[0]), "+f"(c[1]), "+f"(c[2]), "+f"(c[3])
        : "r"(a.x), "r"(a.y), "r"(a.z), "r"(a.w), "r"(b.x), "r"(b.y));
}

// ---------------- pre: self-loop attr + degree ---------------------------------
__global__ void k_init_pre() {
    int i = blockIdx.x * blockDim.x + threadIdx.x;
    if (i < NN * BONDD) g_loopsum[i] = 0.f;
    if (i < NN) { g_deg[i] = 0.f; g_degi[i] = 0; }
}

__global__ void k_degattr(const int* __restrict__ dst, const float* __restrict__ ea) {
    int j = blockIdx.x * blockDim.x + threadIdx.x;
    if (j >= EE * BONDD) return;
    int e = j / BONDD, b = j - e * BONDD;
    int d = dst[e];
    atomicAdd(&g_loopsum[d * BONDD + b], ea[j]);
    if (b == 0) { atomicAdd(&g_deg[d], 1.f); atomicAdd(&g_degi[d], 1); }
}

__global__ void k_loopdiv() {
    int j = blockIdx.x * blockDim.x + threadIdx.x;
    if (j >= NN * BONDD) return;
    int n = j / BONDD;
    g_loop[j] = g_loopsum[j] / fmaxf(g_deg[n], 1.f);
}

// ---------------- CSR: scan + fill --------------------------------------------
__global__ void k_scan() {
    __shared__ int sums[1024];
    int t = threadIdx.x;
    int base = t * 8;
    int loc[8];
    int s = 0;
    #pragma unroll
    for (int i = 0; i < 8; i++) {
        loc[i] = s;
        int idx = base + i;
        s += (idx < NN) ? g_degi[idx] : 0;
    }
    sums[t] = s;
    __syncthreads();
    for (int off = 1; off < 1024; off <<= 1) {
        int v = (t >= off) ? sums[t - off] : 0;
        __syncthreads();
        sums[t] += v;
        __syncthreads();
    }
    int pre = (t == 0) ? 0 : sums[t - 1];
    #pragma unroll
    for (int i = 0; i < 8; i++) {
        int idx = base + i;
        if (idx < NN) { g_csroff[idx] = pre + loc[i]; g_cur[idx] = pre + loc[i]; }
    }
    if (t == 0) g_csroff[NN] = EE;
}

__global__ void k_fill(const int* __restrict__ dst) {
    int e = blockIdx.x * blockDim.x + threadIdx.x;
    if (e >= EE) return;
    int d = dst[e];
    int pos = atomicAdd(&g_cur[d], 1);
    g_csre[pos] = e;
}

// ---------------- W -> tf32 B-fragment-major layout ---------------------------
__global__ void k_prepW(const float* __restrict__ Wl, const float* __restrict__ Wr) {
    int z = blockIdx.y;  // 0..9 = l*2+which
    const float* W = ((z & 1) ? Wr : Wl) + (size_t)(z >> 1) * WELEM;
    int idx = blockIdx.x * 256 + threadIdx.x;
    int k = idx >> 11;
    int n = idx & 2047;
    float v = tf32r(W[idx]);
    int blk = (n >> 3) * 32 + (k >> 3);
    int lane = (n & 7) * 4 + (k & 3);
    int slot = (k >> 2) & 1;
    g_Wf[(size_t)z * WELEM + blk * 64 + lane * 2 + slot] = v;
}

// ---------------- atom embedding: relu(LN(x @ W + b)) ------------------------
__global__ void k_embed(const float* __restrict__ x, const float* __restrict__ W,
                        const float* __restrict__ b, const float* __restrict__ g,
                        const float* __restrict__ be) {
    int n = blockIdx.x, tid = threadIdx.x;
    __shared__ float sx[ATOMD];
    __shared__ float rs[8], rq[8];
    if (tid < ATOMD) sx[tid] = x[n * ATOMD + tid];
    __syncthreads();
    float acc = b[tid];
    for (int k = 0; k < ATOMD; k++) acc += sx[k] * W[k * HD + tid];
    float a = acc, q = acc * acc;
    #pragma unroll
    for (int o = 16; o; o >>= 1) {
        a += __shfl_xor_sync(~0u, a, o);
        q += __shfl_xor_sync(~0u, q, o);
    }
    int lane = tid & 31, w = tid >> 5;
    if (!lane) { rs[w] = a; rq[w] = q; }
    __syncthreads();
    float sum = 0.f, sq = 0.f;
    #pragma unroll
    for (int i = 0; i < 8; i++) { sum += rs[i]; sq += rq[i]; }
    float mean = sum * (1.f / HD);
    float var = sq * (1.f / HD) - mean * mean;
    float y = (acc - mean) * rsqrtf(var + 1e-5f) * g[tid] + be[tid];
    y = fmaxf(y, 0.f);
    g_h[n * HD + tid] = y;
    store_frag_h(n, tid, y);
}

// ---------------- tf32 mma GEMM: C = h[8000,256] @ W[256,2048] ----------------
__global__ void __launch_bounds__(256, 2) k_gemm_mma(int l) {
    extern __shared__ uint32_t sm[];
    const int t = threadIdx.x;
    const int warp = t >> 5, lane = t & 31;
    const int wm = warp & 3, wn = warp >> 2;
    const int gr = lane >> 2, tg = lane & 3;
    const int m0 = blockIdx.y * 128, n0 = blockIdx.x * 128;
    const int wi = l * 2 + blockIdx.z;
    float* C = blockIdx.z ? g_xr : g_xl;
    const float* Ab = g_hf + (size_t)(m0 >> 4) * 32 * 128;
    const float* Bb = g_Wf + (size_t)wi * WELEM + (size_t)(n0 >> 3) * 32 * 64;
    const uint32_t sbase = smem_u32(sm);

    float c[2][8][4];
    #pragma unroll
    for (int i = 0; i < 2; i++)
        #pragma unroll
        for (int j = 0; j < 8; j++)
            #pragma unroll
            for (int k = 0; k < 4; k++) c[i][j][k] = 0.f;

    #define PREFETCH(kt, s) do { \
        int kb0 = (kt) * 4; \
        _Pragma("unroll") \
        for (int p = 0; p < 4; p++) { \
            int u = p * 256 + t; \
            int i = u >> 7, q = u & 127; \
            const float* srcA = Ab + (i * 32 + kb0) * 128 + q * 4; \
            CP16(sbase + (s) * 16384 + (i * 512 + q * 4) * 4, srcA); \
        } \
        _Pragma("unroll") \
        for (int p = 0; p < 4; p++) { \
            int u = p * 256 + t; \
            int nb = u >> 6, q = u & 63; \
            const float* srcB = Bb + (nb * 32 + kb0) * 64 + q * 4; \
            CP16(sbase + 32768 + (s) * 16384 + (nb * 256 + q * 4) * 4, srcB); \
        } \
        asm volatile("cp.async.commit_group;" ::: "memory"); \
    } while (0)

    PREFETCH(0, 0);
    for (int kt = 0; kt < 8; kt++) {
        int s = kt & 1;
        if (kt < 7) {
            PREFETCH(kt + 1, s ^ 1);
            asm volatile("cp.async.wait_group 1;" ::: "memory");
        } else {
            asm volatile("cp.async.wait_group 0;" ::: "memory");
        }
        __syncthreads();
        const uint32_t* A = sm + s * 4096;
        const uint32_t* B = sm + 8192 + s * 4096;
        #pragma unroll
        for (int ks = 0; ks < 4; ks++) {
            uint4 a[2];
            a[0] = *(const uint4*)&A[((wm * 2 + 0) * 4 + ks) * 128 + lane * 4];
            a[1] = *(const uint4*)&A[((wm * 2 + 1) * 4 + ks) * 128 + lane * 4];
            uint2 b[8];
            #pragma unroll
            for (int jn = 0; jn < 8; jn++)
                b[jn] = *(const uint2*)&B[((wn * 8 + jn) * 4 + ks) * 64 + lane * 2];
            #pragma unroll
            for (int jn = 0; jn < 8; jn++)
                #pragma unroll
                for (int im = 0; im < 2; im++)
                    mma_tf32(c[im][jn], a[im], b[jn]);
        }
        __syncthreads();
    }
    #undef PREFETCH

    #pragma unroll
    for (int im = 0; im < 2; im++) {
        #pragma unroll
        for (int jn = 0; jn < 8; jn++) {
            int row = m0 + wm * 32 + im * 16 + gr;
            int col = n0 + wn * 64 + jn * 8 + tg * 2;
            if (row < NN)
                *(float2*)&C[(size_t)row * HHD + col] = make_float2(c[im][jn][0], c[im][jn][1]);
            if (row + 8 < NN)
                *(float2*)&C[(size_t)(row + 8) * HHD + col] = make_float2(c[im][jn][2], c[im][jn][3]);
        }
    }
}

// ---------------- fused attention: score+softmax+message+residual+LN ----------
// one block per destination node, 256 threads, no global atomics.
__global__ void __launch_bounds__(256) k_attn(
    const int* __restrict__ src, const float* __restrict__ edge_attr,
    const float* __restrict__ We_l, const float* __restrict__ att_l,
    const float* __restrict__ bias_l, const float* __restrict__ lng,
    const float* __restrict__ lnb) {
    int d = blockIdx.x, t = threadIdx.x;
    __shared__ int s_eid[MAXD];
    __shared__ int s_src[MAXD + 8];
    __shared__ float2 s_ea2[MAXD + 4][8];
    __shared__ float s_sc[8][MAXD + 1];
    __shared__ float s_red[8][8];
    __shared__ float rs[8], rq[8];

    int off = g_csroff[d];
    int deg = g_csroff[d + 1] - off;
    if (deg > MAXD - 1) deg = MAXD - 1;   // unreachable for this dataset
    int ne = deg + 1;                      // + self loop

    for (int i = t; i < deg; i += 256) {
        int e = g_csre[off + i];
        s_eid[i] = e;
        s_src[i] = src[e];
    }
    if (t < 8) s_src[deg + t] = d;        // self-loop + padding
    __syncthreads();
    // edge attrs as float2 (14 floats = 7 float2 per edge)
    for (int j = t; j < ne * 7; j += 256) {
        int i = j / 7, b2 = j - i * 7;
        const float* p = (i < deg) ? (edge_attr + (size_t)s_eid[i] * BONDD)
                                   : (g_loop + (size_t)d * BONDD);
        s_ea2[i][b2] = *(const float2*)(p + 2 * b2);
    }
    for (int j = t; j < 28; j += 256)
        s_ea2[ne + j / 7][j % 7] = make_float2(0.f, 0.f);

    float xr8[8], att8[8];
    #pragma unroll
    for (int h = 0; h < 8; h++) {
        xr8[h] = g_xr[(size_t)d * HHD + h * 256 + t];
        att8[h] = att_l[h * 256 + t];
    }
    __syncthreads();
    int lane = t & 31, w = t >> 5;

    // --- phase 1: scores (chunks of 4 edges; We hoisted per chunk) ---
    for (int i0 = 0; i0 < ne; i0 += 4) {
        int nc = min(4, ne - i0);
        float xlv[4][8];
        #pragma unroll
        for (int i = 0; i < 4; i++) {
            const float* xlr = g_xl + (size_t)s_src[i0 + i] * HHD;
            #pragma unroll
            for (int h = 0; h < 8; h++) xlv[i][h] = xlr[h * 256 + t];
        }
        float ee[4][8];
        #pragma unroll
        for (int i = 0; i < 4; i++)
            #pragma unroll
            for (int h = 0; h < 8; h++) ee[i][h] = 0.f;
        #pragma unroll
        for (int h = 0; h < 8; h++) {
            int hc = h * 256 + t;
            #pragma unroll
            for (int b2 = 0; b2 < 7; b2++) {
                float w0 = We_l[(2 * b2) * HHD + hc];
                float w1 = We_l[(2 * b2 + 1) * HHD + hc];
                #pragma unroll
                for (int i = 0; i < 4; i++) {
                    float2 sv = s_ea2[i0 + i][b2];
                    ee[i][h] += sv.x * w0 + sv.y * w1;
                }
            }
        }
        for (int i = 0; i < nc; i++) {
            float part[8];
            #pragma unroll
            for (int h = 0; h < 8; h++) {
                float v = xlv[i][h] + xr8[h] + ee[i][h];
                v = v > 0.f ? v : 0.2f * v;
                part[h] = v * att8[h];
            }
            #pragma unroll
            for (int h = 0; h < 8; h++) {
                float v = part[h];
                #pragma unroll
                for (int o = 16; o; o >>= 1) v += __shfl_xor_sync(~0u, v, o);
                if (!lane) s_red[h][w] = v;
            }
            __syncthreads();
            if (t < 8) {
                float v = 0.f;
                #pragma unroll
                for (int q = 0; q < 8; q++) v += s_red[t][q];
                s_sc[t][i0 + i] = v;
            }
            __syncthreads();
        }
    }

    // --- softmax per head (local, no atomics) ---
    if (t < 8) {
        float m = -3.4e38f;
        for (int i = 0; i < ne; i++) m = fmaxf(m, s_sc[t][i]);
        float sum = 0.f;
        for (int i = 0; i < ne; i++) {
            float e = expf(s_sc[t][i] - m);
            s_sc[t][i] = e;
            sum += e;
        }
        float inv = 1.f / sum;
        for (int i = 0; i < ne; i++) s_sc[t][i] *= inv;
    }
    __syncthreads();

    // --- phase 2: message (xl reads L1-hot), head mean ---
    float acc = 0.f;
    for (int i = 0; i < ne; i++) {
        const float* xlr = g_xl + (size_t)s_src[i] * HHD;
        #pragma unroll
        for (int h = 0; h < 8; h++) acc += xlr[h * 256 + t] * s_sc[h][i];
    }

    // --- residual + LayerNorm + fragment store ---
    float v = 0.125f * acc + bias_l[t] + g_h[d * HD + t];
    float a = v, q = v * v;
    #pragma unroll
    for (int o = 16; o; o >>= 1) {
        a += __shfl_xor_sync(~0u, a, o);
        q += __shfl_xor_sync(~0u, q, o);
    }
    if (!lane) { rs[w] = a; rq[w] = q; }
    __syncthreads();
    float sum = 0.f, sq = 0.f;
    #pragma unroll
    for (int i = 0; i < 8; i++) { sum += rs[i]; sq += rq[i]; }
    float mean = sum * (1.f / HD);
    float var = sq * (1.f / HD) - mean * mean;
    float y = (v - mean) * rsqrtf(var + 1e-5f) * lng[t] + lnb[t];
    g_h[d * HD + t] = y;
    store_frag_h(d, t, y);
}

// ---------------- readout -----------------------------------------------------
__global__ void k_initread(float* __restrict__ out) {
    int i = blockIdx.x * blockDim.x + threadIdx.x;
    if (i < BB * HD) out[i] = 0.f;
    if (i < BB) { g_gm[i] = ENC_NEG_INF; g_gs[i] = 0.f; }
}

__global__ void k_gate(const float* __restrict__ W1, const float* __restrict__ b1,
                       const float* __restrict__ W2, const float* __restrict__ b2,
                       const int* __restrict__ batch) {
    int n = blockIdx.x, tid = threadIdx.x;
    __shared__ float sh[HD];
    __shared__ float rs[4];
    sh[tid] = g_h[n * HD + tid];
    sh[tid + 128] = g_h[n * HD + tid + 128];
    __syncthreads();
    float acc = b1[tid];
    for (int k = 0; k < HD; k++) acc += sh[k] * W1[k * 128 + tid];
    float part = fmaxf(acc, 0.f) * W2[tid];
    #pragma unroll
    for (int o = 16; o; o >>= 1) part += __shfl_xor_sync(~0u, part, o);
    int lane = tid & 31, w = tid >> 5;
    if (!lane) rs[w] = part;
    __syncthreads();
    if (tid == 0) {
        float gate = rs[0] + rs[1] + rs[2] + rs[3] + b2[0];
        g_gate[n] = gate;
        atomicMax(&g_gm[batch[n]], fenc(gate));
    }
}

__global__ void k_gexp(const int* __restrict__ batch) {
    int n = blockIdx.x * blockDim.x + threadIdx.x;
    if (n >= NN) return;
    int b = batch[n];
    float ge = expf(g_gate[n] - fdec(g_gm[b]));
    g_ge[n] = ge;
    atomicAdd(&g_gs[b], ge);
}

__global__ void k_readout(const int* __restrict__ batch, float* __restrict__ out) {
    int n = blockIdx.x, tid = threadIdx.x;
    int b = batch[n];
    float w = g_ge[n] / fmaxf(g_gs[b], 1e-16f);
    atomicAdd(&out[b * HD + tid], w * g_h[n * HD + tid]);
}

// ---------------- launcher ----------------------------------------------------
extern "C" void kernel_launch(void* const* d_in, const int* in_sizes, int n_in,
                              void* d_out, int out_size) {
    const float* x         = (const float*)d_in[0];
    const float* edge_attr = (const float*)d_in[1];
    const float* emb_W     = (const float*)d_in[2];
    const float* emb_b     = (const float*)d_in[3];
    const float* emb_g     = (const float*)d_in[4];
    const float* emb_beta  = (const float*)d_in[5];
    const float* Wl        = (const float*)d_in[6];
    const float* Wr        = (const float*)d_in[7];
    const float* We        = (const float*)d_in[8];
    const float* att       = (const float*)d_in[9];
    const float* bias      = (const float*)d_in[10];
    const float* ln_g      = (const float*)d_in[11];
    const float* ln_b      = (const float*)d_in[12];
    const float* g1W       = (const float*)d_in[13];
    const float* g1b       = (const float*)d_in[14];
    const float* g2W       = (const float*)d_in[15];
    const float* g2b       = (const float*)d_in[16];
    const int* edge_index  = (const int*)d_in[17];
    const int* batch       = (const int*)d_in[18];
    const int* src = edge_index;
    const int* dst = edge_index + EE;
    float* out = (float*)d_out;

    cudaFuncSetAttribute(k_gemm_mma, cudaFuncAttributeMaxDynamicSharedMemorySize, 65536);

    k_init_pre<<<(NN * BONDD + 255) / 256, 256>>>();
    k_degattr<<<(EE * BONDD + 255) / 256, 256>>>(dst, edge_attr);
    k_loopdiv<<<(NN * BONDD + 255) / 256, 256>>>();
    k_scan<<<1, 1024>>>();
    k_fill<<<(EE + 255) / 256, 256>>>(dst);
    k_prepW<<<dim3(WELEM / 256, 10), 256>>>(Wl, Wr);
    k_embed<<<NN, HD>>>(x, emb_W, emb_b, emb_g, emb_beta);

    dim3 gg(HHD / 128, (NN + 127) / 128, 2);
    for (int l = 0; l < NLAYERS; l++) {
        k_gemm_mma<<<gg, 256, 65536>>>(l);
        k_attn<<<NN, HD>>>(src, edge_attr,
                           We + (size_t)l * BONDD * HHD,
                           att + (size_t)l * NHEADS * HD,
                           bias + l * HD, ln_g + l * HD, ln_b + l * HD);
    }

    k_initread<<<(BB * HD + 255) / 256, 256>>>(out);
    k_gate<<<NN, 128>>>(g1W, g1b, g2W, g2b, batch);
    k_gexp<<<(NN + 255) / 256, 256>>>(batch);
    k_readout<<<NN, HD>>>(batch, out);
}

// round 9
// speedup vs baseline: 1.4600x; 1.4600x over previous
#include <cuda_runtime.h>
#include <math.h>
#include <stdint.h>

#define NN 8000
#define EE 24000
#define EAA 32000
#define BB 256
#define ATOMD 133
#define BONDD 14
#define HD 256
#define NHEADS 8
#define HHD 2048
#define NLAYERS 5
#define EPB 4                    // edges per score-block

#define MBLK 504                 // ceil(8064/16) m-fragment blocks
#define WELEM (HD * HHD)         // 524288 floats per weight matrix

// ---------------- scratch (device globals; no allocation allowed) -------------
__device__ float g_h[NN * HD];
__device__ float g_out[NN * HD];
__device__ float g_xl[NN * HHD];
__device__ float g_xr[NN * HHD];
__device__ float g_score[EAA * NHEADS];
__device__ unsigned g_m[NN * NHEADS];
__device__ float g_s[NN * NHEADS];
__device__ float g_deg[NN];
__device__ float g_loopsum[NN * BONDD];
__device__ float g_loop[NN * BONDD];
__device__ float g_gate[NN];
__device__ float g_ge[NN];
__device__ unsigned g_gm[BB];
__device__ float g_gs[BB];
// tf32-rounded, mma-fragment-major copies
__device__ float g_hf[MBLK * 32 * 128];     // A fragments
__device__ float g_Wf[10 * WELEM];          // B fragments

__device__ __forceinline__ unsigned fenc(float f) {
    unsigned u = __float_as_uint(f);
    return (u & 0x80000000u) ? ~u : (u | 0x80000000u);
}
__device__ __forceinline__ float fdec(unsigned u) {
    u = (u & 0x80000000u) ? (u & 0x7FFFFFFFu) : ~u;
    return __uint_as_float(u);
}
#define ENC_NEG_INF 0x007FFFFFu

__device__ __forceinline__ float tf32r(float f) {
    uint32_t u;
    asm("cvt.rna.tf32.f32 %0, %1;" : "=r"(u) : "f"(f));
    return __uint_as_float(u);
}

// A-fragment store: element (m, k) of h -> fragment-major global layout.
__device__ __forceinline__ void store_frag_h(int m, int k, float v) {
    int blk = (m >> 4) * 32 + (k >> 3);
    int lane = (m & 7) * 4 + (k & 3);
    int slot = ((m >> 3) & 1) | (((k >> 2) & 1) << 1);
    g_hf[blk * 128 + lane * 4 + slot] = tf32r(v);
}

#define CP16(dst, src) \
    asm volatile("cp.async.cg.shared.global [%0], [%1], 16;" \
                 :: "r"(dst), "l"(src) : "memory")

__device__ __forceinline__ uint32_t smem_u32(const void* p) {
    uint32_t a;
    asm("{ .reg .u64 t; cvta.to.shared.u64 t, %1; cvt.u32.u64 %0, t; }"
        : "=r"(a) : "l"(p));
    return a;
}

__device__ __forceinline__ void mma_tf32(float* c, const uint4& a, const uint2& b) {
    asm volatile(
        "mma.sync.aligned.m16n8k8.row.col.f32.tf32.tf32.f32 "
        "{%0,%1,%2,%3}, {%4,%5,%6,%7}, {%8,%9}, {%0,%1,%2,%3};\n"
        : "+f"(c[0]), "+f"(c[1]), "+f"(c[2]), "+f"(c[3])
        : "r"(a.x), "r"(a.y), "r"(a.z), "r"(a.w), "r"(b.x), "r"(b.y));
}

// ---------------- pre: self-loop attr = mean of incoming edge_attr ------------
__global__ void k_init_pre() {
    int i = blockIdx.x * blockDim.x + threadIdx.x;
    if (i < NN * BONDD) g_loopsum[i] = 0.f;
    if (i < NN) g_deg[i] = 0.f;
}

__global__ void k_degattr(const int* __restrict__ dst, const float* __restrict__ ea) {
    int j = blockIdx.x * blockDim.x + threadIdx.x;
    if (j >= EE * BONDD) return;
    int e = j / BONDD, b = j - e * BONDD;
    int d = dst[e];
    atomicAdd(&g_loopsum[d * BONDD + b], ea[j]);
    if (b == 0) atomicAdd(&g_deg[d], 1.f);
}

__global__ void k_loopdiv() {
    int j = blockIdx.x * blockDim.x + threadIdx.x;
    if (j >= NN * BONDD) return;
    int n = j / BONDD;
    g_loop[j] = g_loopsum[j] / fmaxf(g_deg[n], 1.f);
}

// ---------------- W -> tf32 B-fragment-major layout ---------------------------
__global__ void k_prepW(const float* __restrict__ Wl, const float* __restrict__ Wr) {
    int z = blockIdx.y;  // 0..9 = l*2+which
    const float* W = ((z & 1) ? Wr : Wl) + (size_t)(z >> 1) * WELEM;
    int idx = blockIdx.x * 256 + threadIdx.x;
    int k = idx >> 11;
    int n = idx & 2047;
    float v = tf32r(W[idx]);
    int blk = (n >> 3) * 32 + (k >> 3);
    int lane = (n & 7) * 4 + (k & 3);
    int slot = (k >> 2) & 1;
    g_Wf[(size_t)z * WELEM + blk * 64 + lane * 2 + slot] = v;
}

// ---------------- atom embedding: relu(LN(x @ W + b)) ------------------------
__global__ void k_embed(const float* __restrict__ x, const float* __restrict__ W,
                        const float* __restrict__ b, const float* __restrict__ g,
                        const float* __restrict__ be) {
    int n = blockIdx.x, tid = threadIdx.x;
    __shared__ float sx[ATOMD];
    __shared__ float rs[8], rq[8];
    if (tid < ATOMD) sx[tid] = x[n * ATOMD + tid];
    __syncthreads();
    float acc = b[tid];
    for (int k = 0; k < ATOMD; k++) acc += sx[k] * W[k * HD + tid];
    float a = acc, q = acc * acc;
    #pragma unroll
    for (int o = 16; o; o >>= 1) {
        a += __shfl_xor_sync(~0u, a, o);
        q += __shfl_xor_sync(~0u, q, o);
    }
    int lane = tid & 31, w = tid >> 5;
    if (!lane) { rs[w] = a; rq[w] = q; }
    __syncthreads();
    float sum = 0.f, sq = 0.f;
    #pragma unroll
    for (int i = 0; i < 8; i++) { sum += rs[i]; sq += rq[i]; }
    float mean = sum * (1.f / HD);
    float var = sq * (1.f / HD) - mean * mean;
    float y = (acc - mean) * rsqrtf(var + 1e-5f) * g[tid] + be[tid];
    y = fmaxf(y, 0.f);
    g_h[n * HD + tid] = y;
    store_frag_h(n, tid, y);
}

// ---------------- tf32 mma GEMM: C = h[8000,256] @ W[256,2048] ----------------
__global__ void __launch_bounds__(256, 2) k_gemm_mma(int l) {
    extern __shared__ uint32_t sm[];
    const int t = threadIdx.x;
    const int warp = t >> 5, lane = t & 31;
    const int wm = warp & 3, wn = warp >> 2;
    const int gr = lane >> 2, tg = lane & 3;
    const int m0 = blockIdx.y * 128, n0 = blockIdx.x * 128;
    const int wi = l * 2 + blockIdx.z;
    float* C = blockIdx.z ? g_xr : g_xl;
    const float* Ab = g_hf + (size_t)(m0 >> 4) * 32 * 128;
    const float* Bb = g_Wf + (size_t)wi * WELEM + (size_t)(n0 >> 3) * 32 * 64;
    const uint32_t sbase = smem_u32(sm);

    float c[2][8][4];
    #pragma unroll
    for (int i = 0; i < 2; i++)
        #pragma unroll
        for (int j = 0; j < 8; j++)
            #pragma unroll
            for (int k = 0; k < 4; k++) c[i][j][k] = 0.f;

    #define PREFETCH(kt, s) do { \
        int kb0 = (kt) * 4; \
        _Pragma("unroll") \
        for (int p = 0; p < 4; p++) { \
            int u = p * 256 + t; \
            int i = u >> 7, q = u & 127; \
            const float* srcA = Ab + (i * 32 + kb0) * 128 + q * 4; \
            CP16(sbase + (s) * 16384 + (i * 512 + q * 4) * 4, srcA); \
        } \
        _Pragma("unroll") \
        for (int p = 0; p < 4; p++) { \
            int u = p * 256 + t; \
            int nb = u >> 6, q = u & 63; \
            const float* srcB = Bb + (nb * 32 + kb0) * 64 + q * 4; \
            CP16(sbase + 32768 + (s) * 16384 + (nb * 256 + q * 4) * 4, srcB); \
        } \
        asm volatile("cp.async.commit_group;" ::: "memory"); \
    } while (0)

    PREFETCH(0, 0);
    for (int kt = 0; kt < 8; kt++) {
        int s = kt & 1;
        if (kt < 7) {
            PREFETCH(kt + 1, s ^ 1);
            asm volatile("cp.async.wait_group 1;" ::: "memory");
        } else {
            asm volatile("cp.async.wait_group 0;" ::: "memory");
        }
        __syncthreads();
        const uint32_t* A = sm + s * 4096;
        const uint32_t* B = sm + 8192 + s * 4096;
        #pragma unroll
        for (int ks = 0; ks < 4; ks++) {
            uint4 a[2];
            a[0] = *(const uint4*)&A[((wm * 2 + 0) * 4 + ks) * 128 + lane * 4];
            a[1] = *(const uint4*)&A[((wm * 2 + 1) * 4 + ks) * 128 + lane * 4];
            uint2 b[8];
            #pragma unroll
            for (int jn = 0; jn < 8; jn++)
                b[jn] = *(const uint2*)&B[((wn * 8 + jn) * 4 + ks) * 64 + lane * 2];
            #pragma unroll
            for (int jn = 0; jn < 8; jn++)
                #pragma unroll
                for (int im = 0; im < 2; im++)
                    mma_tf32(c[im][jn], a[im], b[jn]);
        }
        __syncthreads();
    }
    #undef PREFETCH

    #pragma unroll
    for (int im = 0; im < 2; im++) {
        #pragma unroll
        for (int jn = 0; jn < 8; jn++) {
            int row = m0 + wm * 32 + im * 16 + gr;
            int col = n0 + wn * 64 + jn * 8 + tg * 2;
            if (row < NN)
                *(float2*)&C[(size_t)row * HHD + col] = make_float2(c[im][jn][0], c[im][jn][1]);
            if (row + 8 < NN)
                *(float2*)&C[(size_t)(row + 8) * HHD + col] = make_float2(c[im][jn][2], c[im][jn][3]);
        }
    }
}

// ---------------- per-layer zero/init -----------------------------------------
__global__ void k_init_layer() {
    int i = blockIdx.x * blockDim.x + threadIdx.x;
    if (i < NN * HD) g_out[i] = 0.f;
    if (i < NN * NHEADS) { g_s[i] = 0.f; g_m[i] = ENC_NEG_INF; }
}

// ---------------- edge score: EPB edges per block, We hoisted ------------------
__global__ void __launch_bounds__(256) k_score(
    const int* __restrict__ src, const int* __restrict__ dst,
    const float* __restrict__ edge_attr,
    const float* __restrict__ We_l, const float* __restrict__ att_l) {
    int e0 = blockIdx.x * EPB, t = threadIdx.x;
    __shared__ float sea[EPB][BONDD];
    __shared__ int ss[EPB], sd[EPB];
    __shared__ float wsum[NHEADS][8];

    if (t < EPB) {
        int e = e0 + t;
        int s, d;
        if (e < EE) { s = src[e]; d = dst[e]; }
        else        { s = d = e - EE; }
        ss[t] = s; sd[t] = d;
    }
    if (t < EPB * BONDD) {
        int i = t / BONDD, b = t - i * BONDD;
        int e = e0 + i;
        sea[i][b] = (e < EE) ? edge_attr[(size_t)e * BONDD + b]
                             : g_loop[(size_t)(e - EE) * BONDD + b];
    }
    __syncthreads();

    float part[EPB][NHEADS];
    #pragma unroll
    for (int h = 0; h < NHEADS; h++) {
        int hc = h * HD + t;
        float ee[EPB];
        #pragma unroll
        for (int i = 0; i < EPB; i++) ee[i] = 0.f;
        #pragma unroll
        for (int b = 0; b < BONDD; b++) {
            float w = We_l[b * HHD + hc];
            #pragma unroll
            for (int i = 0; i < EPB; i++) ee[i] += sea[i][b] * w;
        }
        float av = att_l[hc];
        #pragma unroll
        for (int i = 0; i < EPB; i++) {
            float v = g_xl[(size_t)ss[i] * HHD + hc] + g_xr[(size_t)sd[i] * HHD + hc] + ee[i];
            v = v > 0.f ? v : 0.2f * v;
            part[i][h] = v * av;
        }
    }

    int lane = t & 31, w = t >> 5;
    for (int i = 0; i < EPB; i++) {
        #pragma unroll
        for (int h = 0; h < NHEADS; h++) {
            float v = part[i][h];
            #pragma unroll
            for (int o = 16; o; o >>= 1) v += __shfl_xor_sync(~0u, v, o);
            if (!lane) wsum[h][w] = v;
        }
        __syncthreads();
        if (t < NHEADS) {
            float v = 0.f;
            #pragma unroll
            for (int q = 0; q < 8; q++) v += wsum[t][q];
            g_score[(e0 + i) * NHEADS + t] = v;
            atomicMax(&g_m[sd[i] * NHEADS + t], fenc(v));
        }
        __syncthreads();
    }
}

// ---------------- exp(score - max) + segment sum ------------------------------
__global__ void k_expsum(const int* __restrict__ dst) {
    int j = blockIdx.x * blockDim.x + threadIdx.x;
    if (j >= EAA * NHEADS) return;
    int e = j / NHEADS, h = j - e * NHEADS;
    int d = (e < EE) ? dst[e] : (e - EE);
    float ex = expf(g_score[j] - fdec(g_m[d * NHEADS + h]));
    g_score[j] = ex;
    atomicAdd(&g_s[d * NHEADS + h], ex);
}

// ---------------- message -----------------------------------------------------
__global__ void k_message(const int* __restrict__ src, const int* __restrict__ dst) {
    int e = blockIdx.x, tid = threadIdx.x;
    __shared__ float alpha[NHEADS];
    int s, d;
    if (e < EE) { s = src[e]; d = dst[e]; }
    else        { s = d = e - EE; }
    if (tid < NHEADS)
        alpha[tid] = g_score[e * NHEADS + tid] / g_s[d * NHEADS + tid];
    __syncthreads();
    const float* xlrow = g_xl + (size_t)s * HHD;
    float acc = 0.f;
    #pragma unroll
    for (int h = 0; h < NHEADS; h++) acc += xlrow[h * HD + tid] * alpha[h];
    atomicAdd(&g_out[d * HD + tid], 0.125f * acc);
}

// ---------------- residual + LayerNorm (+ fragment store) ---------------------
__global__ void k_resln(const float* __restrict__ bias_l, const float* __restrict__ g,
                        const float* __restrict__ be) {
    int n = blockIdx.x, tid = threadIdx.x;
    __shared__ float rs[8], rq[8];
    float v = g_out[n * HD + tid] + bias_l[tid] + g_h[n * HD + tid];
    float a = v, q = v * v;
    #pragma unroll
    for (int o = 16; o; o >>= 1) {
        a += __shfl_xor_sync(~0u, a, o);
        q += __shfl_xor_sync(~0u, q, o);
    }
    int lane = tid & 31, w = tid >> 5;
    if (!lane) { rs[w] = a; rq[w] = q; }
    __syncthreads();
    float sum = 0.f, sq = 0.f;
    #pragma unroll
    for (int i = 0; i < 8; i++) { sum += rs[i]; sq += rq[i]; }
    float mean = sum * (1.f / HD);
    float var = sq * (1.f / HD) - mean * mean;
    float y = (v - mean) * rsqrtf(var + 1e-5f) * g[tid] + be[tid];
    g_h[n * HD + tid] = y;
    store_frag_h(n, tid, y);
}

// ---------------- readout -----------------------------------------------------
__global__ void k_initread(float* __restrict__ out) {
    int i = blockIdx.x * blockDim.x + threadIdx.x;
    if (i < BB * HD) out[i] = 0.f;
    if (i < BB) { g_gm[i] = ENC_NEG_INF; g_gs[i] = 0.f; }
}

__global__ void k_gate(const float* __restrict__ W1, const float* __restrict__ b1,
                       const float* __restrict__ W2, const float* __restrict__ b2,
                       const int* __restrict__ batch) {
    int n = blockIdx.x, tid = threadIdx.x;
    __shared__ float sh[HD];
    __shared__ float rs[4];
    sh[tid] = g_h[n * HD + tid];
    sh[tid + 128] = g_h[n * HD + tid + 128];
    __syncthreads();
    float acc = b1[tid];
    for (int k = 0; k < HD; k++) acc += sh[k] * W1[k * 128 + tid];
    float part = fmaxf(acc, 0.f) * W2[tid];
    #pragma unroll
    for (int o = 16; o; o >>= 1) part += __shfl_xor_sync(~0u, part, o);
    int lane = tid & 31, w = tid >> 5;
    if (!lane) rs[w] = part;
    __syncthreads();
    if (tid == 0) {
        float gate = rs[0] + rs[1] + rs[2] + rs[3] + b2[0];
        g_gate[n] = gate;
        atomicMax(&g_gm[batch[n]], fenc(gate));
    }
}

__global__ void k_gexp(const int* __restrict__ batch) {
    int n = blockIdx.x * blockDim.x + threadIdx.x;
    if (n >= NN) return;
    int b = batch[n];
    float ge = expf(g_gate[n] - fdec(g_gm[b]));
    g_ge[n] = ge;
    atomicAdd(&g_gs[b], ge);
}

__global__ void k_readout(const int* __restrict__ batch, float* __restrict__ out) {
    int n = blockIdx.x, tid = threadIdx.x;
    int b = batch[n];
    float w = g_ge[n] / fmaxf(g_gs[b], 1e-16f);
    atomicAdd(&out[b * HD + tid], w * g_h[n * HD + tid]);
}

// ---------------- launcher ----------------------------------------------------
extern "C" void kernel_launch(void* const* d_in, const int* in_sizes, int n_in,
                              void* d_out, int out_size) {
    const float* x         = (const float*)d_in[0];
    const float* edge_attr = (const float*)d_in[1];
    const float* emb_W     = (const float*)d_in[2];
    const float* emb_b     = (const float*)d_in[3];
    const float* emb_g     = (const float*)d_in[4];
    const float* emb_beta  = (const float*)d_in[5];
    const float* Wl        = (const float*)d_in[6];
    const float* Wr        = (const float*)d_in[7];
    const float* We        = (const float*)d_in[8];
    const float* att       = (const float*)d_in[9];
    const float* bias      = (const float*)d_in[10];
    const float* ln_g      = (const float*)d_in[11];
    const float* ln_b      = (const float*)d_in[12];
    const float* g1W       = (const float*)d_in[13];
    const float* g1b       = (const float*)d_in[14];
    const float* g2W       = (const float*)d_in[15];
    const float* g2b       = (const float*)d_in[16];
    const int* edge_index  = (const int*)d_in[17];
    const int* batch       = (const int*)d_in[18];
    const int* src = edge_index;
    const int* dst = edge_index + EE;
    float* out = (float*)d_out;

    cudaFuncSetAttribute(k_gemm_mma, cudaFuncAttributeMaxDynamicSharedMemorySize, 65536);

    k_init_pre<<<(NN * BONDD + 255) / 256, 256>>>();
    k_degattr<<<(EE * BONDD + 255) / 256, 256>>>(dst, edge_attr);
    k_loopdiv<<<(NN * BONDD + 255) / 256, 256>>>();
    k_prepW<<<dim3(WELEM / 256, 10), 256>>>(Wl, Wr);
    k_embed<<<NN, HD>>>(x, emb_W, emb_b, emb_g, emb_beta);

    dim3 gg(HHD / 128, (NN + 127) / 128, 2);
    for (int l = 0; l < NLAYERS; l++) {
        k_init_layer<<<(NN * HD + 255) / 256, 256>>>();
        k_gemm_mma<<<gg, 256, 65536>>>(l);
        k_score<<<EAA / EPB, HD>>>(src, dst, edge_attr,
                                   We + (size_t)l * BONDD * HHD,
                                   att + (size_t)l * NHEADS * HD);
        k_expsum<<<(EAA * NHEADS + 255) / 256, 256>>>(dst);
        k_message<<<EAA, HD>>>(src, dst);
        k_resln<<<NN, HD>>>(bias + l * HD, ln_g + l * HD, ln_b + l * HD);
    }

    k_initread<<<(BB * HD + 255) / 256, 256>>>(out);
    k_gate<<<NN, 128>>>(g1W, g1b, g2W, g2b, batch);
    k_gexp<<<(NN + 255) / 256, 256>>>(batch);
    k_readout<<<NN, HD>>>(batch, out);
}

// round 11
// speedup vs baseline: 2.1347x; 1.4621x over previous
#include <cuda_runtime.h>
#include <math.h>
#include <stdint.h>

#define NN 8000
#define EE 24000
#define EAA 32000
#define BB 256
#define ATOMD 133
#define BONDD 14
#define HD 256
#define NHEADS 8
#define HHD 2048
#define NLAYERS 5

#define MBLK 504                 // ceil(8064/16) m-fragment blocks
#define WELEM (HD * HHD)         // 524288 floats per weight matrix

// ---------------- scratch (device globals; no allocation allowed) -------------
__device__ float g_h[NN * HD];
__device__ float g_out[NN * HD];
__device__ float g_xl[NN * HHD];
__device__ float g_xr[NN * HHD];
__device__ float g_score[EAA * NHEADS];
__device__ unsigned g_m[NN * NHEADS];
__device__ float g_s[NN * NHEADS];
__device__ float g_deg[NN];
__device__ float g_loopsum[NN * BONDD];
__device__ float g_loop[NN * BONDD];
__device__ float g_ea[EAA * BONDD];         // unified edge attrs (incl. self loops)
__device__ float g_ee[(size_t)EAA * HHD];   // ea @ We[l], rebuilt per layer
__device__ float g_gate[NN];
__device__ float g_ge[NN];
__device__ unsigned g_gm[BB];
__device__ float g_gs[BB];
// tf32-rounded, mma-fragment-major copies
__device__ float g_hf[MBLK * 32 * 128];     // A fragments
__device__ float g_Wf[10 * WELEM];          // B fragments

__device__ __forceinline__ unsigned fenc(float f) {
    unsigned u = __float_as_uint(f);
    return (u & 0x80000000u) ? ~u : (u | 0x80000000u);
}
__device__ __forceinline__ float fdec(unsigned u) {
    u = (u & 0x80000000u) ? (u & 0x7FFFFFFFu) : ~u;
    return __uint_as_float(u);
}
#define ENC_NEG_INF 0x007FFFFFu

__device__ __forceinline__ float tf32r(float f) {
    uint32_t u;
    asm("cvt.rna.tf32.f32 %0, %1;" : "=r"(u) : "f"(f));
    return __uint_as_float(u);
}

// A-fragment store: element (m, k) of h -> fragment-major global layout.
__device__ __forceinline__ void store_frag_h(int m, int k, float v) {
    int blk = (m >> 4) * 32 + (k >> 3);
    int lane = (m & 7) * 4 + (k & 3);
    int slot = ((m >> 3) & 1) | (((k >> 2) & 1) << 1);
    g_hf[blk * 128 + lane * 4 + slot] = tf32r(v);
}

#define CP16(dst, src) \
    asm volatile("cp.async.cg.shared.global [%0], [%1], 16;" \
                 :: "r"(dst), "l"(src) : "memory")

__device__ __forceinline__ uint32_t smem_u32(const void* p) {
    uint32_t a;
    asm("{ .reg .u64 t; cvta.to.shared.u64 t, %1; cvt.u32.u64 %0, t; }"
        : "=r"(a) : "l"(p));
    return a;
}

__device__ __forceinline__ void mma_tf32(float* c, const uint4& a, const uint2& b) {
    asm volatile(
        "mma.sync.aligned.m16n8k8.row.col.f32.tf32.tf32.f32 "
        "{%0,%1,%2,%3}, {%4,%5,%6,%7}, {%8,%9}, {%0,%1,%2,%3};\n"
        : "+f"(c[0]), "+f"(c[1]), "+f"(c[2]), "+f"(c[3])
        : "r"(a.x), "r"(a.y), "r"(a.z), "r"(a.w), "r"(b.x), "r"(b.y));
}

// ---------------- pre: self-loop attr = mean of incoming edge_attr ------------
__global__ void k_init_pre() {
    int i = blockIdx.x * blockDim.x + threadIdx.x;
    if (i < NN * BONDD) g_loopsum[i] = 0.f;
    if (i < NN) g_deg[i] = 0.f;
}

__global__ void k_degattr(const int* __restrict__ dst, const float* __restrict__ ea) {
    int j = blockIdx.x * blockDim.x + threadIdx.x;
    if (j >= EE * BONDD) return;
    int e = j / BONDD, b = j - e * BONDD;
    int d = dst[e];
    atomicAdd(&g_loopsum[d * BONDD + b], ea[j]);
    if (b == 0) atomicAdd(&g_deg[d], 1.f);
}

__global__ void k_loopdiv() {
    int j = blockIdx.x * blockDim.x + threadIdx.x;
    if (j >= NN * BONDD) return;
    int n = j / BONDD;
    g_loop[j] = g_loopsum[j] / fmaxf(g_deg[n], 1.f);
}

// unified edge-attr table: real edges then self loops
__global__ void k_buildea(const float* __restrict__ edge_attr) {
    int j = blockIdx.x * blockDim.x + threadIdx.x;
    if (j >= EAA * BONDD) return;
    g_ea[j] = (j < EE * BONDD) ? edge_attr[j] : g_loop[j - EE * BONDD];
}

// ---------------- W -> tf32 B-fragment-major layout ---------------------------
__global__ void k_prepW(const float* __restrict__ Wl, const float* __restrict__ Wr) {
    int z = blockIdx.y;  // 0..9 = l*2+which
    const float* W = ((z & 1) ? Wr : Wl) + (size_t)(z >> 1) * WELEM;
    int idx = blockIdx.x * 256 + threadIdx.x;
    int k = idx >> 11;
    int n = idx & 2047;
    float v = tf32r(W[idx]);
    int blk = (n >> 3) * 32 + (k >> 3);
    int lane = (n & 7) * 4 + (k & 3);
    int slot = (k >> 2) & 1;
    g_Wf[(size_t)z * WELEM + blk * 64 + lane * 2 + slot] = v;
}

// ---------------- atom embedding: relu(LN(x @ W + b)) + per-layer resets -------
__global__ void k_embed(const float* __restrict__ x, const float* __restrict__ W,
                        const float* __restrict__ b, const float* __restrict__ g,
                        const float* __restrict__ be) {
    int n = blockIdx.x, tid = threadIdx.x;
    __shared__ float sx[ATOMD];
    __shared__ float rs[8], rq[8];
    if (tid < ATOMD) sx[tid] = x[n * ATOMD + tid];
    __syncthreads();
    float acc = b[tid];
    for (int k = 0; k < ATOMD; k++) acc += sx[k] * W[k * HD + tid];
    float a = acc, q = acc * acc;
    #pragma unroll
    for (int o = 16; o; o >>= 1) {
        a += __shfl_xor_sync(~0u, a, o);
        q += __shfl_xor_sync(~0u, q, o);
    }
    int lane = tid & 31, w = tid >> 5;
    if (!lane) { rs[w] = a; rq[w] = q; }
    __syncthreads();
    float sum = 0.f, sq = 0.f;
    #pragma unroll
    for (int i = 0; i < 8; i++) { sum += rs[i]; sq += rq[i]; }
    float mean = sum * (1.f / HD);
    float var = sq * (1.f / HD) - mean * mean;
    float y = (acc - mean) * rsqrtf(var + 1e-5f) * g[tid] + be[tid];
    y = fmaxf(y, 0.f);
    g_h[n * HD + tid] = y;
    store_frag_h(n, tid, y);
    // layer-0 resets (folded from k_init_layer)
    g_out[n * HD + tid] = 0.f;
    if (tid < NHEADS) { g_s[n * NHEADS + tid] = 0.f; g_m[n * NHEADS + tid] = ENC_NEG_INF; }
}

// ---------------- tf32 mma GEMM: C = h[8000,256] @ W[256,2048] ----------------
__global__ void __launch_bounds__(256, 2) k_gemm_mma(int l) {
    extern __shared__ uint32_t sm[];
    const int t = threadIdx.x;
    const int warp = t >> 5, lane = t & 31;
    const int wm = warp & 3, wn = warp >> 2;
    const int gr = lane >> 2, tg = lane & 3;
    const int m0 = blockIdx.y * 128, n0 = blockIdx.x * 128;
    const int wi = l * 2 + blockIdx.z;
    float* C = blockIdx.z ? g_xr : g_xl;
    const float* Ab = g_hf + (size_t)(m0 >> 4) * 32 * 128;
    const float* Bb = g_Wf + (size_t)wi * WELEM + (size_t)(n0 >> 3) * 32 * 64;
    const uint32_t sbase = smem_u32(sm);

    float c[2][8][4];
    #pragma unroll
    for (int i = 0; i < 2; i++)
        #pragma unroll
        for (int j = 0; j < 8; j++)
            #pragma unroll
            for (int k = 0; k < 4; k++) c[i][j][k] = 0.f;

    #define PREFETCH(kt, s) do { \
        int kb0 = (kt) * 4; \
        _Pragma("unroll") \
        for (int p = 0; p < 4; p++) { \
            int u = p * 256 + t; \
            int i = u >> 7, q = u & 127; \
            const float* srcA = Ab + (i * 32 + kb0) * 128 + q * 4; \
            CP16(sbase + (s) * 16384 + (i * 512 + q * 4) * 4, srcA); \
        } \
        _Pragma("unroll") \
        for (int p = 0; p < 4; p++) { \
            int u = p * 256 + t; \
            int nb = u >> 6, q = u & 63; \
            const float* srcB = Bb + (nb * 32 + kb0) * 64 + q * 4; \
            CP16(sbase + 32768 + (s) * 16384 + (nb * 256 + q * 4) * 4, srcB); \
        } \
        asm volatile("cp.async.commit_group;" ::: "memory"); \
    } while (0)

    PREFETCH(0, 0);
    for (int kt = 0; kt < 8; kt++) {
        int s = kt & 1;
        if (kt < 7) {
            PREFETCH(kt + 1, s ^ 1);
            asm volatile("cp.async.wait_group 1;" ::: "memory");
        } else {
            asm volatile("cp.async.wait_group 0;" ::: "memory");
        }
        __syncthreads();
        const uint32_t* A = sm + s * 4096;
        const uint32_t* B = sm + 8192 + s * 4096;
        #pragma unroll
        for (int ks = 0; ks < 4; ks++) {
            uint4 a[2];
            a[0] = *(const uint4*)&A[((wm * 2 + 0) * 4 + ks) * 128 + lane * 4];
            a[1] = *(const uint4*)&A[((wm * 2 + 1) * 4 + ks) * 128 + lane * 4];
            uint2 b[8];
            #pragma unroll
            for (int jn = 0; jn < 8; jn++)
                b[jn] = *(const uint2*)&B[((wn * 8 + jn) * 4 + ks) * 64 + lane * 2];
            #pragma unroll
            for (int jn = 0; jn < 8; jn++)
                #pragma unroll
                for (int im = 0; im < 2; im++)
                    mma_tf32(c[im][jn], a[im], b[jn]);
        }
        __syncthreads();
    }
    #undef PREFETCH

    #pragma unroll
    for (int im = 0; im < 2; im++) {
        #pragma unroll
        for (int jn = 0; jn < 8; jn++) {
            int row = m0 + wm * 32 + im * 16 + gr;
            int col = n0 + wn * 64 + jn * 8 + tg * 2;
            if (row < NN)
                *(float2*)&C[(size_t)row * HHD + col] = make_float2(c[im][jn][0], c[im][jn][1]);
            if (row + 8 < NN)
                *(float2*)&C[(size_t)(row + 8) * HHD + col] = make_float2(c[im][jn][2], c[im][jn][3]);
        }
    }
}

// ---------------- ee = ea @ We[l]  (We hoisted into registers) ----------------
// grid (EAA/32, HHD/256), 256 threads; each thread: one col x 32 edges.
__global__ void __launch_bounds__(256) k_ee(const float* __restrict__ We_l) {
    __shared__ float sea[32][BONDD];
    int e0 = blockIdx.x * 32, t = threadIdx.x;
    for (int i = t; i < 32 * BONDD; i += 256)
        sea[i / BONDD][i % BONDD] = g_ea[e0 * BONDD + i];
    int col = blockIdx.y * 256 + t;
    float w[BONDD];
    #pragma unroll
    for (int b = 0; b < BONDD; b++) w[b] = We_l[b * HHD + col];
    __syncthreads();
    #pragma unroll 4
    for (int e = 0; e < 32; e++) {
        float acc = 0.f;
        #pragma unroll
        for (int b = 0; b < BONDD; b++) acc = fmaf(sea[e][b], w[b], acc);
        g_ee[(size_t)(e0 + e) * HHD + col] = acc;
    }
}

// ---------------- edge score: leaky(xl[s]+xr[d]+ee) . att ---------------------
__global__ void k_score(const int* __restrict__ src, const int* __restrict__ dst,
                        const float* __restrict__ att_l) {
    int e = blockIdx.x, tid = threadIdx.x;
    __shared__ float wsum[NHEADS * 8];
    int s, d;
    if (e < EE) { s = src[e]; d = dst[e]; }
    else        { s = d = e - EE; }
    const float* xlrow = g_xl + (size_t)s * HHD;
    const float* xrrow = g_xr + (size_t)d * HHD;
    const float* eerow = g_ee + (size_t)e * HHD;
    float part[NHEADS];
    #pragma unroll
    for (int h = 0; h < NHEADS; h++) {
        int cc = h * HD + tid;
        float v = xlrow[cc] + xrrow[cc] + eerow[cc];
        v = v > 0.f ? v : 0.2f * v;
        part[h] = v * att_l[cc];
    }
    int lane = tid & 31, w = tid >> 5;
    #pragma unroll
    for (int h = 0; h < NHEADS; h++) {
        float v = part[h];
        #pragma unroll
        for (int o = 16; o; o >>= 1) v += __shfl_xor_sync(~0u, v, o);
        if (!lane) wsum[h * 8 + w] = v;
    }
    __syncthreads();
    if (tid < NHEADS) {
        float v = 0.f;
        #pragma unroll
        for (int w2 = 0; w2 < 8; w2++) v += wsum[tid * 8 + w2];
        g_score[e * NHEADS + tid] = v;
        atomicMax(&g_m[d * NHEADS + tid], fenc(v));
    }
}

// ---------------- exp(score - max) + segment sum ------------------------------
__global__ void k_expsum(const int* __restrict__ dst) {
    int j = blockIdx.x * blockDim.x + threadIdx.x;
    if (j >= EAA * NHEADS) return;
    int e = j / NHEADS, h = j - e * NHEADS;
    int d = (e < EE) ? dst[e] : (e - EE);
    float ex = expf(g_score[j] - fdec(g_m[d * NHEADS + h]));
    g_score[j] = ex;
    atomicAdd(&g_s[d * NHEADS + h], ex);
}

// ---------------- message -----------------------------------------------------
__global__ void k_message(const int* __restrict__ src, const int* __restrict__ dst) {
    int e = blockIdx.x, tid = threadIdx.x;
    __shared__ float alpha[NHEADS];
    int s, d;
    if (e < EE) { s = src[e]; d = dst[e]; }
    else        { s = d = e - EE; }
    if (tid < NHEADS)
        alpha[tid] = g_score[e * NHEADS + tid] / g_s[d * NHEADS + tid];
    __syncthreads();
    const float* xlrow = g_xl + (size_t)s * HHD;
    float acc = 0.f;
    #pragma unroll
    for (int h = 0; h < NHEADS; h++) acc += xlrow[h * HD + tid] * alpha[h];
    atomicAdd(&g_out[d * HD + tid], 0.125f * acc);
}

// ---------------- residual + LayerNorm + fragment store + resets --------------
__global__ void k_resln(const float* __restrict__ bias_l, const float* __restrict__ g,
                        const float* __restrict__ be) {
    int n = blockIdx.x, tid = threadIdx.x;
    __shared__ float rs[8], rq[8];
    float v = g_out[n * HD + tid] + bias_l[tid] + g_h[n * HD + tid];
    // reset accumulators for next layer (folded from k_init_layer)
    g_out[n * HD + tid] = 0.f;
    if (tid < NHEADS) { g_s[n * NHEADS + tid] = 0.f; g_m[n * NHEADS + tid] = ENC_NEG_INF; }
    float a = v, q = v * v;
    #pragma unroll
    for (int o = 16; o; o >>= 1) {
        a += __shfl_xor_sync(~0u, a, o);
        q += __shfl_xor_sync(~0u, q, o);
    }
    int lane = tid & 31, w = tid >> 5;
    if (!lane) { rs[w] = a; rq[w] = q; }
    __syncthreads();
    float sum = 0.f, sq = 0.f;
    #pragma unroll
    for (int i = 0; i < 8; i++) { sum += rs[i]; sq += rq[i]; }
    float mean = sum * (1.f / HD);
    float var = sq * (1.f / HD) - mean * mean;
    float y = (v - mean) * rsqrtf(var + 1e-5f) * g[tid] + be[tid];
    g_h[n * HD + tid] = y;
    store_frag_h(n, tid, y);
}

// ---------------- readout -----------------------------------------------------
__global__ void k_initread(float* __restrict__ out) {
    int i = blockIdx.x * blockDim.x + threadIdx.x;
    if (i < BB * HD) out[i] = 0.f;
    if (i < BB) { g_gm[i] = ENC_NEG_INF; g_gs[i] = 0.f; }
}

__global__ void k_gate(const float* __restrict__ W1, const float* __restrict__ b1,
                       const float* __restrict__ W2, const float* __restrict__ b2,
                       const int* __restrict__ batch) {
    int n = blockIdx.x, tid = threadIdx.x;
    __shared__ float sh[HD];
    __shared__ float rs[4];
    sh[tid] = g_h[n * HD + tid];
    sh[tid + 128] = g_h[n * HD + tid + 128];
    __syncthreads();
    float acc = b1[tid];
    for (int k = 0; k < HD; k++) acc += sh[k] * W1[k * 128 + tid];
    float part = fmaxf(acc, 0.f) * W2[tid];
    #pragma unroll
    for (int o = 16; o; o >>= 1) part += __shfl_xor_sync(~0u, part, o);
    int lane = tid & 31, w = tid >> 5;
    if (!lane) rs[w] = part;
    __syncthreads();
    if (tid == 0) {
        float gate = rs[0] + rs[1] + rs[2] + rs[3] + b2[0];
        g_gate[n] = gate;
        atomicMax(&g_gm[batch[n]], fenc(gate));
    }
}

__global__ void k_gexp(const int* __restrict__ batch) {
    int n = blockIdx.x * blockDim.x + threadIdx.x;
    if (n >= NN) return;
    int b = batch[n];
    float ge = expf(g_gate[n] - fdec(g_gm[b]));
    g_ge[n] = ge;
    atomicAdd(&g_gs[b], ge);
}

__global__ void k_readout(const int* __restrict__ batch, float* __restrict__ out) {
    int n = blockIdx.x, tid = threadIdx.x;
    int b = batch[n];
    float w = g_ge[n] / fmaxf(g_gs[b], 1e-16f);
    atomicAdd(&out[b * HD + tid], w * g_h[n * HD + tid]);
}

// ---------------- launcher ----------------------------------------------------
extern "C" void kernel_launch(void* const* d_in, const int* in_sizes, int n_in,
                              void* d_out, int out_size) {
    const float* x         = (const float*)d_in[0];
    const float* edge_attr = (const float*)d_in[1];
    const float* emb_W     = (const float*)d_in[2];
    const float* emb_b     = (const float*)d_in[3];
    const float* emb_g     = (const float*)d_in[4];
    const float* emb_beta  = (const float*)d_in[5];
    const float* Wl        = (const float*)d_in[6];
    const float* Wr        = (const float*)d_in[7];
    const float* We        = (const float*)d_in[8];
    const float* att       = (const float*)d_in[9];
    const float* bias      = (const float*)d_in[10];
    const float* ln_g      = (const float*)d_in[11];
    const float* ln_b      = (const float*)d_in[12];
    const float* g1W       = (const float*)d_in[13];
    const float* g1b       = (const float*)d_in[14];
    const float* g2W       = (const float*)d_in[15];
    const float* g2b       = (const float*)d_in[16];
    const int* edge_index  = (const int*)d_in[17];
    const int* batch       = (const int*)d_in[18];
    const int* src = edge_index;
    const int* dst = edge_index + EE;
    float* out = (float*)d_out;

    cudaFuncSetAttribute(k_gemm_mma, cudaFuncAttributeMaxDynamicSharedMemorySize, 65536);

    k_init_pre<<<(NN * BONDD + 255) / 256, 256>>>();
    k_degattr<<<(EE * BONDD + 255) / 256, 256>>>(dst, edge_attr);
    k_loopdiv<<<(NN * BONDD + 255) / 256, 256>>>();
    k_buildea<<<(EAA * BONDD + 255) / 256, 256>>>(edge_attr);
    k_prepW<<<dim3(WELEM / 256, 10), 256>>>(Wl, Wr);
    k_embed<<<NN, HD>>>(x, emb_W, emb_b, emb_g, emb_beta);

    dim3 gg(HHD / 128, (NN + 127) / 128, 2);
    dim3 ge(EAA / 32, HHD / 256);
    for (int l = 0; l < NLAYERS; l++) {
        k_gemm_mma<<<gg, 256, 65536>>>(l);
        k_ee<<<ge, 256>>>(We + (size_t)l * BONDD * HHD);
        k_score<<<EAA, HD>>>(src, dst, att + (size_t)l * NHEADS * HD);
        k_expsum<<<(EAA * NHEADS + 255) / 256, 256>>>(dst);
        k_message<<<EAA, HD>>>(src, dst);
        k_resln<<<NN, HD>>>(bias + l * HD, ln_g + l * HD, ln_b + l * HD);
    }

    k_initread<<<(BB * HD + 255) / 256, 256>>>(out);
    k_gate<<<NN, 128>>>(g1W, g1b, g2W, g2b, batch);
    k_gexp<<<(NN + 255) / 256, 256>>>(batch);
    k_readout<<<NN, HD>>>(batch, out);
}

// round 13
// speedup vs baseline: 2.3013x; 1.0780x over previous
#include <cuda_runtime.h>
#include <math.h>
#include <stdint.h>

#define NN 8000
#define EE 24000
#define EAA 32000
#define BB 256
#define ATOMD 133
#define BONDD 14
#define HD 256
#define NHEADS 8
#define HHD 2048
#define NLAYERS 5
#define MAXD 64

#define MBLK 504                 // ceil(8064/16) m-fragment blocks
#define WELEM (HD * HHD)         // 524288 floats per weight matrix

// ---------------- scratch (device globals; no allocation allowed) -------------
__device__ float g_h[NN * HD];
__device__ float g_xl[NN * HHD];
__device__ float g_xr[NN * HHD];
__device__ float g_score[EAA * NHEADS];     // raw scores
__device__ float g_deg[NN];
__device__ float g_loopsum[NN * BONDD];
__device__ float g_loop[NN * BONDD];
__device__ float g_ea[EAA * BONDD];         // unified edge attrs (incl. self loops)
__device__ float g_gate[NN];
__device__ float g_ge[NN];
__device__ unsigned g_gm[BB];
__device__ float g_gs[BB];
// CSR by destination
__device__ int g_degi[NN];
__device__ int g_csroff[NN + 1];
__device__ int g_cur[NN];
__device__ int g_csre[EE];
// tf32-rounded, mma-fragment-major copies
__device__ float g_hf[MBLK * 32 * 128];     // A fragments
__device__ float g_Wf[10 * WELEM];          // B fragments

__device__ __forceinline__ unsigned fenc(float f) {
    unsigned u = __float_as_uint(f);
    return (u & 0x80000000u) ? ~u : (u | 0x80000000u);
}
__device__ __forceinline__ float fdec(unsigned u) {
    u = (u & 0x80000000u) ? (u & 0x7FFFFFFFu) : ~u;
    return __uint_as_float(u);
}
#define ENC_NEG_INF 0x007FFFFFu

__device__ __forceinline__ float tf32r(float f) {
    uint32_t u;
    asm("cvt.rna.tf32.f32 %0, %1;" : "=r"(u) : "f"(f));
    return __uint_as_float(u);
}

// A-fragment store: element (m, k) of h -> fragment-major global layout.
__device__ __forceinline__ void store_frag_h(int m, int k, float v) {
    int blk = (m >> 4) * 32 + (k >> 3);
    int lane = (m & 7) * 4 + (k & 3);
    int slot = ((m >> 3) & 1) | (((k >> 2) & 1) << 1);
    g_hf[blk * 128 + lane * 4 + slot] = tf32r(v);
}

#define CP16(dst, src) \
    asm volatile("cp.async.cg.shared.global [%0], [%1], 16;" \
                 :: "r"(dst), "l"(src) : "memory")

__device__ __forceinline__ uint32_t smem_u32(const void* p) {
    uint32_t a;
    asm("{ .reg .u64 t; cvta.to.shared.u64 t, %1; cvt.u32.u64 %0, t; }"
        : "=r"(a) : "l"(p));
    return a;
}

__device__ __forceinline__ void mma_tf32(float* c, const uint4& a, const uint2& b) {
    asm volatile(
        "mma.sync.aligned.m16n8k8.row.col.f32.tf32.tf32.f32 "
        "{%0,%1,%2,%3}, {%4,%5,%6,%7}, {%8,%9}, {%0,%1,%2,%3};\n"
        : "+f"(c[0]), "+f"(c[1]), "+f"(c[2]), "+f"(c[3])
        : "r"(a.x), "r"(a.y), "r"(a.z), "r"(a.w), "r"(b.x), "r"(b.y));
}

// ---------------- pre: self-loop attr + degree ---------------------------------
__global__ void k_init_pre() {
    int i = blockIdx.x * blockDim.x + threadIdx.x;
    if (i < NN * BONDD) g_loopsum[i] = 0.f;
    if (i < NN) { g_deg[i] = 0.f; g_degi[i] = 0; }
}

__global__ void k_degattr(const int* __restrict__ dst, const float* __restrict__ ea) {
    int j = blockIdx.x * blockDim.x + threadIdx.x;
    if (j >= EE * BONDD) return;
    int e = j / BONDD, b = j - e * BONDD;
    int d = dst[e];
    atomicAdd(&g_loopsum[d * BONDD + b], ea[j]);
    if (b == 0) { atomicAdd(&g_deg[d], 1.f); atomicAdd(&g_degi[d], 1); }
}

__global__ void k_loopdiv() {
    int j = blockIdx.x * blockDim.x + threadIdx.x;
    if (j >= NN * BONDD) return;
    int n = j / BONDD;
    g_loop[j] = g_loopsum[j] / fmaxf(g_deg[n], 1.f);
}

// unified edge-attr table: real edges then self loops
__global__ void k_buildea(const float* __restrict__ edge_attr) {
    int j = blockIdx.x * blockDim.x + threadIdx.x;
    if (j >= EAA * BONDD) return;
    g_ea[j] = (j < EE * BONDD) ? edge_attr[j] : g_loop[j - EE * BONDD];
}

// ---------------- CSR: scan + fill --------------------------------------------
__global__ void k_scan() {
    __shared__ int sums[1024];
    int t = threadIdx.x;
    int base = t * 8;
    int loc[8];
    int s = 0;
    #pragma unroll
    for (int i = 0; i < 8; i++) {
        loc[i] = s;
        int idx = base + i;
        s += (idx < NN) ? g_degi[idx] : 0;
    }
    sums[t] = s;
    __syncthreads();
    for (int off = 1; off < 1024; off <<= 1) {
        int v = (t >= off) ? sums[t - off] : 0;
        __syncthreads();
        sums[t] += v;
        __syncthreads();
    }
    int pre = (t == 0) ? 0 : sums[t - 1];
    #pragma unroll
    for (int i = 0; i < 8; i++) {
        int idx = base + i;
        if (idx < NN) { g_csroff[idx] = pre + loc[i]; g_cur[idx] = pre + loc[i]; }
    }
    if (t == 0) g_csroff[NN] = EE;
}

__global__ void k_fill(const int* __restrict__ dst) {
    int e = blockIdx.x * blockDim.x + threadIdx.x;
    if (e >= EE) return;
    int d = dst[e];
    int pos = atomicAdd(&g_cur[d], 1);
    g_csre[pos] = e;
}

// ---------------- W -> tf32 B-fragment-major layout ---------------------------
__global__ void k_prepW(const float* __restrict__ Wl, const float* __restrict__ Wr) {
    int z = blockIdx.y;  // 0..9 = l*2+which
    const float* W = ((z & 1) ? Wr : Wl) + (size_t)(z >> 1) * WELEM;
    int idx = blockIdx.x * 256 + threadIdx.x;
    int k = idx >> 11;
    int n = idx & 2047;
    float v = tf32r(W[idx]);
    int blk = (n >> 3) * 32 + (k >> 3);
    int lane = (n & 7) * 4 + (k & 3);
    int slot = (k >> 2) & 1;
    g_Wf[(size_t)z * WELEM + blk * 64 + lane * 2 + slot] = v;
}

// ---------------- atom embedding: relu(LN(x @ W + b)) -------------------------
__global__ void k_embed(const float* __restrict__ x, const float* __restrict__ W,
                        const float* __restrict__ b, const float* __restrict__ g,
                        const float* __restrict__ be) {
    int n = blockIdx.x, tid = threadIdx.x;
    __shared__ float sx[ATOMD];
    __shared__ float rs[8], rq[8];
    if (tid < ATOMD) sx[tid] = x[n * ATOMD + tid];
    __syncthreads();
    float acc = b[tid];
    for (int k = 0; k < ATOMD; k++) acc += sx[k] * W[k * HD + tid];
    float a = acc, q = acc * acc;
    #pragma unroll
    for (int o = 16; o; o >>= 1) {
        a += __shfl_xor_sync(~0u, a, o);
        q += __shfl_xor_sync(~0u, q, o);
    }
    int lane = tid & 31, w = tid >> 5;
    if (!lane) { rs[w] = a; rq[w] = q; }
    __syncthreads();
    float sum = 0.f, sq = 0.f;
    #pragma unroll
    for (int i = 0; i < 8; i++) { sum += rs[i]; sq += rq[i]; }
    float mean = sum * (1.f / HD);
    float var = sq * (1.f / HD) - mean * mean;
    float y = (acc - mean) * rsqrtf(var + 1e-5f) * g[tid] + be[tid];
    y = fmaxf(y, 0.f);
    g_h[n * HD + tid] = y;
    store_frag_h(n, tid, y);
}

// ---------------- tf32 mma GEMM: C = h[8000,256] @ W[256,2048] ----------------
__global__ void __launch_bounds__(256, 2) k_gemm_mma(int l) {
    extern __shared__ uint32_t sm[];
    const int t = threadIdx.x;
    const int warp = t >> 5, lane = t & 31;
    const int wm = warp & 3, wn = warp >> 2;
    const int gr = lane >> 2, tg = lane & 3;
    const int m0 = blockIdx.y * 128, n0 = blockIdx.x * 128;
    const int wi = l * 2 + blockIdx.z;
    float* C = blockIdx.z ? g_xr : g_xl;
    const float* Ab = g_hf + (size_t)(m0 >> 4) * 32 * 128;
    const float* Bb = g_Wf + (size_t)wi * WELEM + (size_t)(n0 >> 3) * 32 * 64;
    const uint32_t sbase = smem_u32(sm);

    float c[2][8][4];
    #pragma unroll
    for (int i = 0; i < 2; i++)
        #pragma unroll
        for (int j = 0; j < 8; j++)
            #pragma unroll
            for (int k = 0; k < 4; k++) c[i][j][k] = 0.f;

    #define PREFETCH(kt, s) do { \
        int kb0 = (kt) * 4; \
        _Pragma("unroll") \
        for (int p = 0; p < 4; p++) { \
            int u = p * 256 + t; \
            int i = u >> 7, q = u & 127; \
            const float* srcA = Ab + (i * 32 + kb0) * 128 + q * 4; \
            CP16(sbase + (s) * 16384 + (i * 512 + q * 4) * 4, srcA); \
        } \
        _Pragma("unroll") \
        for (int p = 0; p < 4; p++) { \
            int u = p * 256 + t; \
            int nb = u >> 6, q = u & 63; \
            const float* srcB = Bb + (nb * 32 + kb0) * 64 + q * 4; \
            CP16(sbase + 32768 + (s) * 16384 + (nb * 256 + q * 4) * 4, srcB); \
        } \
        asm volatile("cp.async.commit_group;" ::: "memory"); \
    } while (0)

    PREFETCH(0, 0);
    for (int kt = 0; kt < 8; kt++) {
        int s = kt & 1;
        if (kt < 7) {
            PREFETCH(kt + 1, s ^ 1);
            asm volatile("cp.async.wait_group 1;" ::: "memory");
        } else {
            asm volatile("cp.async.wait_group 0;" ::: "memory");
        }
        __syncthreads();
        const uint32_t* A = sm + s * 4096;
        const uint32_t* B = sm + 8192 + s * 4096;
        #pragma unroll
        for (int ks = 0; ks < 4; ks++) {
            uint4 a[2];
            a[0] = *(const uint4*)&A[((wm * 2 + 0) * 4 + ks) * 128 + lane * 4];
            a[1] = *(const uint4*)&A[((wm * 2 + 1) * 4 + ks) * 128 + lane * 4];
            uint2 b[8];
            #pragma unroll
            for (int jn = 0; jn < 8; jn++)
                b[jn] = *(const uint2*)&B[((wn * 8 + jn) * 4 + ks) * 64 + lane * 2];
            #pragma unroll
            for (int jn = 0; jn < 8; jn++)
                #pragma unroll
                for (int im = 0; im < 2; im++)
                    mma_tf32(c[im][jn], a[im], b[jn]);
        }
        __syncthreads();
    }
    #undef PREFETCH

    #pragma unroll
    for (int im = 0; im < 2; im++) {
        #pragma unroll
        for (int jn = 0; jn < 8; jn++) {
            int row = m0 + wm * 32 + im * 16 + gr;
            int col = n0 + wn * 64 + jn * 8 + tg * 2;
            if (row < NN)
                *(float2*)&C[(size_t)row * HHD + col] = make_float2(c[im][jn][0], c[im][jn][1]);
            if (row + 8 < NN)
                *(float2*)&C[(size_t)(row + 8) * HHD + col] = make_float2(c[im][jn][2], c[im][jn][3]);
        }
    }
}

// ---------------- fused score: leaky(xl[s]+xr[d]+ea@We) . att -----------------
// grid (EAA/32, NHEADS); block = 32 edges x 1 head; We in registers.
__global__ void __launch_bounds__(256) k_score2(
    const int* __restrict__ src, const int* __restrict__ dst,
    const float* __restrict__ We_l, const float* __restrict__ att_l) {
    __shared__ float sea[32][BONDD];
    __shared__ int ssrc[32], sdst[32];
    __shared__ float prod[32][257];
    int e0 = blockIdx.x * 32, h = blockIdx.y, t = threadIdx.x;
    int col = h * HD + t;

    for (int j = t; j < 32 * BONDD; j += 256)
        sea[j / BONDD][j % BONDD] = g_ea[e0 * BONDD + j];
    if (t < 32) {
        int e = e0 + t;
        ssrc[t] = (e < EE) ? src[e] : (e - EE);
        sdst[t] = (e < EE) ? dst[e] : (e - EE);
    }
    float w[BONDD];
    #pragma unroll
    for (int b = 0; b < BONDD; b++) w[b] = We_l[b * HHD + col];
    float av = att_l[col];
    __syncthreads();

    #pragma unroll 4
    for (int e = 0; e < 32; e++) {
        float ee = 0.f;
        #pragma unroll
        for (int b = 0; b < BONDD; b++) ee = fmaf(sea[e][b], w[b], ee);
        float v = g_xl[(size_t)ssrc[e] * HHD + col] +
                  g_xr[(size_t)sdst[e] * HHD + col] + ee;
        v = v > 0.f ? v : 0.2f * v;
        prod[e][t] = v * av;
    }
    __syncthreads();

    // reduce 256 cols per edge: 8 threads per edge, stride-8 reads (<=4-way cfl)
    int e = t >> 3, sub = t & 7;
    float acc = 0.f;
    #pragma unroll
    for (int i = 0; i < 32; i++) acc += prod[e][sub + 8 * i];
    #pragma unroll
    for (int o = 4; o; o >>= 1) acc += __shfl_xor_sync(~0u, acc, o);
    if (sub == 0) g_score[(e0 + e) * NHEADS + h] = acc;
}

// ---------------- fused message: local softmax + gather + residual + LN -------
// one block per destination node; no atomics.
__global__ void __launch_bounds__(256) k_msgln(
    const int* __restrict__ src, const float* __restrict__ bias_l,
    const float* __restrict__ lng, const float* __restrict__ lnb) {
    int d = blockIdx.x, t = threadIdx.x;
    __shared__ int s_src[MAXD];
    __shared__ float s_alpha[NHEADS][MAXD];
    __shared__ float rs[8], rq[8];

    int off = g_csroff[d];
    int deg = g_csroff[d + 1] - off;
    if (deg > MAXD - 1) deg = MAXD - 1;
    int ne = deg + 1;                     // + self loop

    for (int i = t; i < deg; i += 256) s_src[i] = src[g_csre[off + i]];
    if (t == 0) s_src[deg] = d;
    // scores: ne * 8 values
    for (int j = t; j < ne * NHEADS; j += 256) {
        int i = j >> 3, h = j & 7;
        int e = (i < deg) ? g_csre[off + i] : (EE + d);
        s_alpha[h][i] = g_score[e * NHEADS + h];
    }
    __syncthreads();

    if (t < NHEADS) {
        float m = -3.4e38f;
        for (int i = 0; i < ne; i++) m = fmaxf(m, s_alpha[t][i]);
        float sum = 0.f;
        for (int i = 0; i < ne; i++) {
            float ex = expf(s_alpha[t][i] - m);
            s_alpha[t][i] = ex;
            sum += ex;
        }
        float inv = 1.f / sum;
        for (int i = 0; i < ne; i++) s_alpha[t][i] *= inv;
    }
    __syncthreads();

    float acc = 0.f;
    for (int i = 0; i < ne; i++) {
        const float* xlr = g_xl + (size_t)s_src[i] * HHD;
        #pragma unroll
        for (int h = 0; h < NHEADS; h++)
            acc = fmaf(xlr[h * HD + t], s_alpha[h][i], acc);
    }

    float v = 0.125f * acc + bias_l[t] + g_h[d * HD + t];
    float a = v, q = v * v;
    #pragma unroll
    for (int o = 16; o; o >>= 1) {
        a += __shfl_xor_sync(~0u, a, o);
        q += __shfl_xor_sync(~0u, q, o);
    }
    int lane = t & 31, w = t >> 5;
    if (!lane) { rs[w] = a; rq[w] = q; }
    __syncthreads();
    float sum = 0.f, sq = 0.f;
    #pragma unroll
    for (int i = 0; i < 8; i++) { sum += rs[i]; sq += rq[i]; }
    float mean = sum * (1.f / HD);
    float var = sq * (1.f / HD) - mean * mean;
    float y = (v - mean) * rsqrtf(var + 1e-5f) * lng[t] + lnb[t];
    g_h[d * HD + t] = y;
    store_frag_h(d, t, y);
}

// ---------------- readout -----------------------------------------------------
__global__ void k_initread(float* __restrict__ out) {
    int i = blockIdx.x * blockDim.x + threadIdx.x;
    if (i < BB * HD) out[i] = 0.f;
    if (i < BB) { g_gm[i] = ENC_NEG_INF; g_gs[i] = 0.f; }
}

__global__ void k_gate(const float* __restrict__ W1, const float* __restrict__ b1,
                       const float* __restrict__ W2, const float* __restrict__ b2,
                       const int* __restrict__ batch) {
    int n = blockIdx.x, tid = threadIdx.x;
    __shared__ float sh[HD];
    __shared__ float rs[4];
    sh[tid] = g_h[n * HD + tid];
    sh[tid + 128] = g_h[n * HD + tid + 128];
    __syncthreads();
    float acc = b1[tid];
    for (int k = 0; k < HD; k++) acc += sh[k] * W1[k * 128 + tid];
    float part = fmaxf(acc, 0.f) * W2[tid];
    #pragma unroll
    for (int o = 16; o; o >>= 1) part += __shfl_xor_sync(~0u, part, o);
    int lane = tid & 31, w = tid >> 5;
    if (!lane) rs[w] = part;
    __syncthreads();
    if (tid == 0) {
        float gate = rs[0] + rs[1] + rs[2] + rs[3] + b2[0];
        g_gate[n] = gate;
        atomicMax(&g_gm[batch[n]], fenc(gate));
    }
}

__global__ void k_gexp(const int* __restrict__ batch) {
    int n = blockIdx.x * blockDim.x + threadIdx.x;
    if (n >= NN) return;
    int b = batch[n];
    float ge = expf(g_gate[n] - fdec(g_gm[b]));
    g_ge[n] = ge;
    atomicAdd(&g_gs[b], ge);
}

__global__ void k_readout(const int* __restrict__ batch, float* __restrict__ out) {
    int n = blockIdx.x, tid = threadIdx.x;
    int b = batch[n];
    float w = g_ge[n] / fmaxf(g_gs[b], 1e-16f);
    atomicAdd(&out[b * HD + tid], w * g_h[n * HD + tid]);
}

// ---------------- launcher ----------------------------------------------------
extern "C" void kernel_launch(void* const* d_in, const int* in_sizes, int n_in,
                              void* d_out, int out_size) {
    const float* x         = (const float*)d_in[0];
    const float* edge_attr = (const float*)d_in[1];
    const float* emb_W     = (const float*)d_in[2];
    const float* emb_b     = (const float*)d_in[3];
    const float* emb_g     = (const float*)d_in[4];
    const float* emb_beta  = (const float*)d_in[5];
    const float* Wl        = (const float*)d_in[6];
    const float* Wr        = (const float*)d_in[7];
    const float* We        = (const float*)d_in[8];
    const float* att       = (const float*)d_in[9];
    const float* bias      = (const float*)d_in[10];
    const float* ln_g      = (const float*)d_in[11];
    const float* ln_b      = (const float*)d_in[12];
    const float* g1W       = (const float*)d_in[13];
    const float* g1b       = (const float*)d_in[14];
    const float* g2W       = (const float*)d_in[15];
    const float* g2b       = (const float*)d_in[16];
    const int* edge_index  = (const int*)d_in[17];
    const int* batch       = (const int*)d_in[18];
    const int* src = edge_index;
    const int* dst = edge_index + EE;
    float* out = (float*)d_out;

    cudaFuncSetAttribute(k_gemm_mma, cudaFuncAttributeMaxDynamicSharedMemorySize, 65536);

    k_init_pre<<<(NN * BONDD + 255) / 256, 256>>>();
    k_degattr<<<(EE * BONDD + 255) / 256, 256>>>(dst, edge_attr);
    k_loopdiv<<<(NN * BONDD + 255) / 256, 256>>>();
    k_buildea<<<(EAA * BONDD + 255) / 256, 256>>>(edge_attr);
    k_scan<<<1, 1024>>>();
    k_fill<<<(EE + 255) / 256, 256>>>(dst);
    k_prepW<<<dim3(WELEM / 256, 10), 256>>>(Wl, Wr);
    k_embed<<<NN, HD>>>(x, emb_W, emb_b, emb_g, emb_beta);

    dim3 gg(HHD / 128, (NN + 127) / 128, 2);
    dim3 gs(EAA / 32, NHEADS);
    for (int l = 0; l < NLAYERS; l++) {
        k_gemm_mma<<<gg, 256, 65536>>>(l);
        k_score2<<<gs, 256>>>(src, dst,
                              We + (size_t)l * BONDD * HHD,
                              att + (size_t)l * NHEADS * HD);
        k_msgln<<<NN, HD>>>(src, bias + l * HD, ln_g + l * HD, ln_b + l * HD);
    }

    k_initread<<<(BB * HD + 255) / 256, 256>>>(out);
    k_gate<<<NN, 128>>>(g1W, g1b, g2W, g2b, batch);
    k_gexp<<<(NN + 255) / 256, 256>>>(batch);
    k_readout<<<NN, HD>>>(batch, out);
}

// round 15
// speedup vs baseline: 2.4317x; 1.0567x over previous
#include <cuda_runtime.h>
#include <cuda_fp16.h>
#include <math.h>
#include <stdint.h>

#define NN 8000
#define EE 24000
#define EAA 32000
#define BB 256
#define ATOMD 133
#define BONDD 14
#define HD 256
#define NHEADS 8
#define HHD 2048
#define NLAYERS 5
#define MAXD 64

#define MBLK 504                 // ceil(8064/16) m-fragment blocks
#define WELEM (HD * HHD)         // 524288 floats per weight matrix

// ---------------- scratch (device globals; no allocation allowed) -------------
__device__ float g_h[NN * HD];
__device__ __half g_xl[NN * HHD];
__device__ __half g_xr[NN * HHD];
__device__ float g_score[EAA * NHEADS];     // raw scores
__device__ float g_deg[NN];
__device__ float g_loopsum[NN * BONDD];
__device__ float g_loop[NN * BONDD];
__device__ float g_ea[EAA * BONDD];         // unified edge attrs (incl. self loops)
__device__ float g_gate[NN];
__device__ float g_ge[NN];
__device__ unsigned g_gm[BB];
__device__ float g_gs[BB];
// CSR by destination
__device__ int g_degi[NN];
__device__ int g_csroff[NN + 1];
__device__ int g_cur[NN];
__device__ int g_csre[EE];
// tf32-rounded, mma-fragment-major copies
__device__ float g_hf[MBLK * 32 * 128];     // A fragments
__device__ float g_Wf[10 * WELEM];          // B fragments

__device__ __forceinline__ unsigned fenc(float f) {
    unsigned u = __float_as_uint(f);
    return (u & 0x80000000u) ? ~u : (u | 0x80000000u);
}
__device__ __forceinline__ float fdec(unsigned u) {
    u = (u & 0x80000000u) ? (u & 0x7FFFFFFFu) : ~u;
    return __uint_as_float(u);
}
#define ENC_NEG_INF 0x007FFFFFu

__device__ __forceinline__ float tf32r(float f) {
    uint32_t u;
    asm("cvt.rna.tf32.f32 %0, %1;" : "=r"(u) : "f"(f));
    return __uint_as_float(u);
}

// A-fragment store: element (m, k) of h -> fragment-major global layout.
__device__ __forceinline__ void store_frag_h(int m, int k, float v) {
    int blk = (m >> 4) * 32 + (k >> 3);
    int lane = (m & 7) * 4 + (k & 3);
    int slot = ((m >> 3) & 1) | (((k >> 2) & 1) << 1);
    g_hf[blk * 128 + lane * 4 + slot] = tf32r(v);
}

#define CP16(dst, src) \
    asm volatile("cp.async.cg.shared.global [%0], [%1], 16;" \
                 :: "r"(dst), "l"(src) : "memory")

__device__ __forceinline__ uint32_t smem_u32(const void* p) {
    uint32_t a;
    asm("{ .reg .u64 t; cvta.to.shared.u64 t, %1; cvt.u32.u64 %0, t; }"
        : "=r"(a) : "l"(p));
    return a;
}

__device__ __forceinline__ void mma_tf32(float* c, const uint4& a, const uint2& b) {
    asm volatile(
        "mma.sync.aligned.m16n8k8.row.col.f32.tf32.tf32.f32 "
        "{%0,%1,%2,%3}, {%4,%5,%6,%7}, {%8,%9}, {%0,%1,%2,%3};\n"
        : "+f"(c[0]), "+f"(c[1]), "+f"(c[2]), "+f"(c[3])
        : "r"(a.x), "r"(a.y), "r"(a.z), "r"(a.w), "r"(b.x), "r"(b.y));
}

// ---------------- pre: self-loop attr + degree ---------------------------------
__global__ void k_init_pre() {
    int i = blockIdx.x * blockDim.x + threadIdx.x;
    if (i < NN * BONDD) g_loopsum[i] = 0.f;
    if (i < NN) { g_deg[i] = 0.f; g_degi[i] = 0; }
}

__global__ void k_degattr(const int* __restrict__ dst, const float* __restrict__ ea) {
    int j = blockIdx.x * blockDim.x + threadIdx.x;
    if (j >= EE * BONDD) return;
    int e = j / BONDD, b = j - e * BONDD;
    int d = dst[e];
    atomicAdd(&g_loopsum[d * BONDD + b], ea[j]);
    if (b == 0) { atomicAdd(&g_deg[d], 1.f); atomicAdd(&g_degi[d], 1); }
}

__global__ void k_loopdiv() {
    int j = blockIdx.x * blockDim.x + threadIdx.x;
    if (j >= NN * BONDD) return;
    int n = j / BONDD;
    g_loop[j] = g_loopsum[j] / fmaxf(g_deg[n], 1.f);
}

// unified edge-attr table: real edges then self loops
__global__ void k_buildea(const float* __restrict__ edge_attr) {
    int j = blockIdx.x * blockDim.x + threadIdx.x;
    if (j >= EAA * BONDD) return;
    g_ea[j] = (j < EE * BONDD) ? edge_attr[j] : g_loop[j - EE * BONDD];
}

// ---------------- CSR: scan + fill --------------------------------------------
__global__ void k_scan() {
    __shared__ int sums[1024];
    int t = threadIdx.x;
    int base = t * 8;
    int loc[8];
    int s = 0;
    #pragma unroll
    for (int i = 0; i < 8; i++) {
        loc[i] = s;
        int idx = base + i;
        s += (idx < NN) ? g_degi[idx] : 0;
    }
    sums[t] = s;
    __syncthreads();
    for (int off = 1; off < 1024; off <<= 1) {
        int v = (t >= off) ? sums[t - off] : 0;
        __syncthreads();
        sums[t] += v;
        __syncthreads();
    }
    int pre = (t == 0) ? 0 : sums[t - 1];
    #pragma unroll
    for (int i = 0; i < 8; i++) {
        int idx = base + i;
        if (idx < NN) { g_csroff[idx] = pre + loc[i]; g_cur[idx] = pre + loc[i]; }
    }
    if (t == 0) g_csroff[NN] = EE;
}

__global__ void k_fill(const int* __restrict__ dst) {
    int e = blockIdx.x * blockDim.x + threadIdx.x;
    if (e >= EE) return;
    int d = dst[e];
    int pos = atomicAdd(&g_cur[d], 1);
    g_csre[pos] = e;
}

// ---------------- W -> tf32 B-fragment-major layout ---------------------------
__global__ void k_prepW(const float* __restrict__ Wl, const float* __restrict__ Wr) {
    int z = blockIdx.y;  // 0..9 = l*2+which
    const float* W = ((z & 1) ? Wr : Wl) + (size_t)(z >> 1) * WELEM;
    int idx = blockIdx.x * 256 + threadIdx.x;
    int k = idx >> 11;
    int n = idx & 2047;
    float v = tf32r(W[idx]);
    int blk = (n >> 3) * 32 + (k >> 3);
    int lane = (n & 7) * 4 + (k & 3);
    int slot = (k >> 2) & 1;
    g_Wf[(size_t)z * WELEM + blk * 64 + lane * 2 + slot] = v;
}

// ---------------- atom embedding: relu(LN(x @ W + b)) -------------------------
__global__ void k_embed(const float* __restrict__ x, const float* __restrict__ W,
                        const float* __restrict__ b, const float* __restrict__ g,
                        const float* __restrict__ be) {
    int n = blockIdx.x, tid = threadIdx.x;
    __shared__ float sx[ATOMD];
    __shared__ float rs[8], rq[8];
    if (tid < ATOMD) sx[tid] = x[n * ATOMD + tid];
    __syncthreads();
    float acc = b[tid];
    for (int k = 0; k < ATOMD; k++) acc += sx[k] * W[k * HD + tid];
    float a = acc, q = acc * acc;
    #pragma unroll
    for (int o = 16; o; o >>= 1) {
        a += __shfl_xor_sync(~0u, a, o);
        q += __shfl_xor_sync(~0u, q, o);
    }
    int lane = tid & 31, w = tid >> 5;
    if (!lane) { rs[w] = a; rq[w] = q; }
    __syncthreads();
    float sum = 0.f, sq = 0.f;
    #pragma unroll
    for (int i = 0; i < 8; i++) { sum += rs[i]; sq += rq[i]; }
    float mean = sum * (1.f / HD);
    float var = sq * (1.f / HD) - mean * mean;
    float y = (acc - mean) * rsqrtf(var + 1e-5f) * g[tid] + be[tid];
    y = fmaxf(y, 0.f);
    g_h[n * HD + tid] = y;
    store_frag_h(n, tid, y);
}

// ---------------- tf32 mma GEMM: C = h[8000,256] @ W[256,2048] (fp16 out) -----
__global__ void __launch_bounds__(256, 2) k_gemm_mma(int l) {
    extern __shared__ uint32_t sm[];
    const int t = threadIdx.x;
    const int warp = t >> 5, lane = t & 31;
    const int wm = warp & 3, wn = warp >> 2;
    const int gr = lane >> 2, tg = lane & 3;
    const int m0 = blockIdx.y * 128, n0 = blockIdx.x * 128;
    const int wi = l * 2 + blockIdx.z;
    __half* C = blockIdx.z ? g_xr : g_xl;
    const float* Ab = g_hf + (size_t)(m0 >> 4) * 32 * 128;
    const float* Bb = g_Wf + (size_t)wi * WELEM + (size_t)(n0 >> 3) * 32 * 64;
    const uint32_t sbase = smem_u32(sm);

    float c[2][8][4];
    #pragma unroll
    for (int i = 0; i < 2; i++)
        #pragma unroll
        for (int j = 0; j < 8; j++)
            #pragma unroll
            for (int k = 0; k < 4; k++) c[i][j][k] = 0.f;

    #define PREFETCH(kt, s) do { \
        int kb0 = (kt) * 4; \
        _Pragma("unroll") \
        for (int p = 0; p < 4; p++) { \
            int u = p * 256 + t; \
            int i = u >> 7, q = u & 127; \
            const float* srcA = Ab + (i * 32 + kb0) * 128 + q * 4; \
            CP16(sbase + (s) * 16384 + (i * 512 + q * 4) * 4, srcA); \
        } \
        _Pragma("unroll") \
        for (int p = 0; p < 4; p++) { \
            int u = p * 256 + t; \
            int nb = u >> 6, q = u & 63; \
            const float* srcB = Bb + (nb * 32 + kb0) * 64 + q * 4; \
            CP16(sbase + 32768 + (s) * 16384 + (nb * 256 + q * 4) * 4, srcB); \
        } \
        asm volatile("cp.async.commit_group;" ::: "memory"); \
    } while (0)

    PREFETCH(0, 0);
    for (int kt = 0; kt < 8; kt++) {
        int s = kt & 1;
        if (kt < 7) {
            PREFETCH(kt + 1, s ^ 1);
            asm volatile("cp.async.wait_group 1;" ::: "memory");
        } else {
            asm volatile("cp.async.wait_group 0;" ::: "memory");
        }
        __syncthreads();
        const uint32_t* A = sm + s * 4096;
        const uint32_t* B = sm + 8192 + s * 4096;
        #pragma unroll
        for (int ks = 0; ks < 4; ks++) {
            uint4 a[2];
            a[0] = *(const uint4*)&A[((wm * 2 + 0) * 4 + ks) * 128 + lane * 4];
            a[1] = *(const uint4*)&A[((wm * 2 + 1) * 4 + ks) * 128 + lane * 4];
            uint2 b[8];
            #pragma unroll
            for (int jn = 0; jn < 8; jn++)
                b[jn] = *(const uint2*)&B[((wn * 8 + jn) * 4 + ks) * 64 + lane * 2];
            #pragma unroll
            for (int jn = 0; jn < 8; jn++)
                #pragma unroll
                for (int im = 0; im < 2; im++)
                    mma_tf32(c[im][jn], a[im], b[jn]);
        }
        __syncthreads();
    }
    #undef PREFETCH

    #pragma unroll
    for (int im = 0; im < 2; im++) {
        #pragma unroll
        for (int jn = 0; jn < 8; jn++) {
            int row = m0 + wm * 32 + im * 16 + gr;
            int col = n0 + wn * 64 + jn * 8 + tg * 2;
            if (row < NN)
                *(__half2*)&C[(size_t)row * HHD + col] =
                    __floats2half2_rn(c[im][jn][0], c[im][jn][1]);
            if (row + 8 < NN)
                *(__half2*)&C[(size_t)(row + 8) * HHD + col] =
                    __floats2half2_rn(c[im][jn][2], c[im][jn][3]);
        }
    }
}

// ---------------- fused score: leaky(xl[s]+xr[d]+ea@We) . att -----------------
// grid (EAA/32, NHEADS); block = 32 edges x 1 head; We in registers.
__global__ void __launch_bounds__(256) k_score2(
    const int* __restrict__ src, const int* __restrict__ dst,
    const float* __restrict__ We_l, const float* __restrict__ att_l) {
    __shared__ float sea[32][BONDD];
    __shared__ int ssrc[32], sdst[32];
    __shared__ float prod[32][257];
    int e0 = blockIdx.x * 32, h = blockIdx.y, t = threadIdx.x;
    int col = h * HD + t;

    for (int j = t; j < 32 * BONDD; j += 256)
        sea[j / BONDD][j % BONDD] = g_ea[e0 * BONDD + j];
    if (t < 32) {
        int e = e0 + t;
        ssrc[t] = (e < EE) ? src[e] : (e - EE);
        sdst[t] = (e < EE) ? dst[e] : (e - EE);
    }
    float w[BONDD];
    #pragma unroll
    for (int b = 0; b < BONDD; b++) w[b] = We_l[b * HHD + col];
    float av = att_l[col];
    __syncthreads();

    #pragma unroll 4
    for (int e = 0; e < 32; e++) {
        float ee = 0.f;
        #pragma unroll
        for (int b = 0; b < BONDD; b++) ee = fmaf(sea[e][b], w[b], ee);
        float v = __half2float(g_xl[(size_t)ssrc[e] * HHD + col]) +
                  __half2float(g_xr[(size_t)sdst[e] * HHD + col]) + ee;
        v = v > 0.f ? v : 0.2f * v;
        prod[e][t] = v * av;
    }
    __syncthreads();

    // reduce 256 cols per edge: 8 threads per edge, stride-8 reads (<=4-way cfl)
    int e = t >> 3, sub = t & 7;
    float acc = 0.f;
    #pragma unroll
    for (int i = 0; i < 32; i++) acc += prod[e][sub + 8 * i];
    #pragma unroll
    for (int o = 4; o; o >>= 1) acc += __shfl_xor_sync(~0u, acc, o);
    if (sub == 0) g_score[(e0 + e) * NHEADS + h] = acc;
}

// ---------------- fused message: local softmax + gather + residual + LN -------
// one block per destination node; no atomics.
__global__ void __launch_bounds__(256) k_msgln(
    const int* __restrict__ src, const float* __restrict__ bias_l,
    const float* __restrict__ lng, const float* __restrict__ lnb) {
    int d = blockIdx.x, t = threadIdx.x;
    __shared__ int s_src[MAXD];
    __shared__ float s_alpha[NHEADS][MAXD];
    __shared__ float rs[8], rq[8];

    int off = g_csroff[d];
    int deg = g_csroff[d + 1] - off;
    if (deg > MAXD - 1) deg = MAXD - 1;
    int ne = deg + 1;                     // + self loop

    for (int i = t; i < deg; i += 256) s_src[i] = src[g_csre[off + i]];
    if (t == 0) s_src[deg] = d;
    // scores: ne * 8 values
    for (int j = t; j < ne * NHEADS; j += 256) {
        int i = j >> 3, h = j & 7;
        int e = (i < deg) ? g_csre[off + i] : (EE + d);
        s_alpha[h][i] = g_score[e * NHEADS + h];
    }
    __syncthreads();

    if (t < NHEADS) {
        float m = -3.4e38f;
        for (int i = 0; i < ne; i++) m = fmaxf(m, s_alpha[t][i]);
        float sum = 0.f;
        for (int i = 0; i < ne; i++) {
            float ex = expf(s_alpha[t][i] - m);
            s_alpha[t][i] = ex;
            sum += ex;
        }
        float inv = 1.f / sum;
        for (int i = 0; i < ne; i++) s_alpha[t][i] *= inv;
    }
    __syncthreads();

    float acc = 0.f;
    for (int i = 0; i < ne; i++) {
        const __half* xlr = g_xl + (size_t)s_src[i] * HHD;
        #pragma unroll
        for (int h = 0; h < NHEADS; h++)
            acc = fmaf(__half2float(xlr[h * HD + t]), s_alpha[h][i], acc);
    }

    float v = 0.125f * acc + bias_l[t] + g_h[d * HD + t];
    float a = v, q = v * v;
    #pragma unroll
    for (int o = 16; o; o >>= 1) {
        a += __shfl_xor_sync(~0u, a, o);
        q += __shfl_xor_sync(~0u, q, o);
    }
    int lane = t & 31, w = t >> 5;
    if (!lane) { rs[w] = a; rq[w] = q; }
    __syncthreads();
    float sum = 0.f, sq = 0.f;
    #pragma unroll
    for (int i = 0; i < 8; i++) { sum += rs[i]; sq += rq[i]; }
    float mean = sum * (1.f / HD);
    float var = sq * (1.f / HD) - mean * mean;
    float y = (v - mean) * rsqrtf(var + 1e-5f) * lng[t] + lnb[t];
    g_h[d * HD + t] = y;
    store_frag_h(d, t, y);
}

// ---------------- readout -----------------------------------------------------
__global__ void k_initread(float* __restrict__ out) {
    int i = blockIdx.x * blockDim.x + threadIdx.x;
    if (i < BB * HD) out[i] = 0.f;
    if (i < BB) { g_gm[i] = ENC_NEG_INF; g_gs[i] = 0.f; }
}

__global__ void k_gate(const float* __restrict__ W1, const float* __restrict__ b1,
                       const float* __restrict__ W2, const float* __restrict__ b2,
                       const int* __restrict__ batch) {
    int n = blockIdx.x, tid = threadIdx.x;
    __shared__ float sh[HD];
    __shared__ float rs[4];
    sh[tid] = g_h[n * HD + tid];
    sh[tid + 128] = g_h[n * HD + tid + 128];
    __syncthreads();
    float acc = b1[tid];
    for (int k = 0; k < HD; k++) acc += sh[k] * W1[k * 128 + tid];
    float part = fmaxf(acc, 0.f) * W2[tid];
    #pragma unroll
    for (int o = 16; o; o >>= 1) part += __shfl_xor_sync(~0u, part, o);
    int lane = tid & 31, w = tid >> 5;
    if (!lane) rs[w] = part;
    __syncthreads();
    if (tid == 0) {
        float gate = rs[0] + rs[1] + rs[2] + rs[3] + b2[0];
        g_gate[n] = gate;
        atomicMax(&g_gm[batch[n]], fenc(gate));
    }
}

__global__ void k_gexp(const int* __restrict__ batch) {
    int n = blockIdx.x * blockDim.x + threadIdx.x;
    if (n >= NN) return;
    int b = batch[n];
    float ge = expf(g_gate[n] - fdec(g_gm[b]));
    g_ge[n] = ge;
    atomicAdd(&g_gs[b], ge);
}

__global__ void k_readout(const int* __restrict__ batch, float* __restrict__ out) {
    int n = blockIdx.x, tid = threadIdx.x;
    int b = batch[n];
    float w = g_ge[n] / fmaxf(g_gs[b], 1e-16f);
    atomicAdd(&out[b * HD + tid], w * g_h[n * HD + tid]);
}

// ---------------- launcher ----------------------------------------------------
extern "C" void kernel_launch(void* const* d_in, const int* in_sizes, int n_in,
                              void* d_out, int out_size) {
    const float* x         = (const float*)d_in[0];
    const float* edge_attr = (const float*)d_in[1];
    const float* emb_W     = (const float*)d_in[2];
    const float* emb_b     = (const float*)d_in[3];
    const float* emb_g     = (const float*)d_in[4];
    const float* emb_beta  = (const float*)d_in[5];
    const float* Wl        = (const float*)d_in[6];
    const float* Wr        = (const float*)d_in[7];
    const float* We        = (const float*)d_in[8];
    const float* att       = (const float*)d_in[9];
    const float* bias      = (const float*)d_in[10];
    const float* ln_g      = (const float*)d_in[11];
    const float* ln_b      = (const float*)d_in[12];
    const float* g1W       = (const float*)d_in[13];
    const float* g1b       = (const float*)d_in[14];
    const float* g2W       = (const float*)d_in[15];
    const float* g2b       = (const float*)d_in[16];
    const int* edge_index  = (const int*)d_in[17];
    const int* batch       = (const int*)d_in[18];
    const int* src = edge_index;
    const int* dst = edge_index + EE;
    float* out = (float*)d_out;

    cudaFuncSetAttribute(k_gemm_mma, cudaFuncAttributeMaxDynamicSharedMemorySize, 65536);

    k_init_pre<<<(NN * BONDD + 255) / 256, 256>>>();
    k_degattr<<<(EE * BONDD + 255) / 256, 256>>>(dst, edge_attr);
    k_loopdiv<<<(NN * BONDD + 255) / 256, 256>>>();
    k_buildea<<<(EAA * BONDD + 255) / 256, 256>>>(edge_attr);
    k_scan<<<1, 1024>>>();
    k_fill<<<(EE + 255) / 256, 256>>>(dst);
    k_prepW<<<dim3(WELEM / 256, 10), 256>>>(Wl, Wr);
    k_embed<<<NN, HD>>>(x, emb_W, emb_b, emb_g, emb_beta);

    dim3 gg(HHD / 128, (NN + 127) / 128, 2);
    dim3 gs(EAA / 32, NHEADS);
    for (int l = 0; l < NLAYERS; l++) {
        k_gemm_mma<<<gg, 256, 65536>>>(l);
        k_score2<<<gs, 256>>>(src, dst,
                              We + (size_t)l * BONDD * HHD,
                              att + (size_t)l * NHEADS * HD);
        k_msgln<<<NN, HD>>>(src, bias + l * HD, ln_g + l * HD, ln_b + l * HD);
    }

    k_initread<<<(BB * HD + 255) / 256, 256>>>(out);
    k_gate<<<NN, 128>>>(g1W, g1b, g2W, g2b, batch);
    k_gexp<<<(NN + 255) / 256, 256>>>(batch);
    k_readout<<<NN, HD>>>(batch, out);
}

// round 16
// speedup vs baseline: 2.6977x; 1.1094x over previous
#include <cuda_runtime.h>
#include <cuda_fp16.h>
#include <math.h>
#include <stdint.h>

#define NN 8000
#define EE 24000
#define EAA 32000
#define BB 256
#define ATOMD 133
#define BONDD 14
#define HD 256
#define NHEADS 8
#define HHD 2048
#define NLAYERS 5
#define MAXD 64

#define MBLK16 504               // padded m-blocks of 16 (ceil(8064/16))
#define WELEM 524288             // halfs per weight matrix (256 nblk * 16 kblk * 128)

// ---------------- scratch (device globals; no allocation allowed) -------------
__device__ float g_h[NN * HD];
__device__ __half g_xl[NN * HHD];
__device__ __half g_xr[NN * HHD];
__device__ float g_score[EAA * NHEADS];     // raw scores
__device__ float g_deg[NN];
__device__ float g_loopsum[NN * BONDD];
__device__ float g_loop[NN * BONDD];
__device__ float g_ea[EAA * BONDD];         // unified edge attrs (incl. self loops)
__device__ float g_gate[NN];
__device__ float g_ge[NN];
__device__ unsigned g_gm[BB];
__device__ float g_gs[BB];
// CSR by destination
__device__ int g_degi[NN];
__device__ int g_csroff[NN + 1];
__device__ int g_cur[NN];
__device__ int g_csre[EE];
// fp16 mma-fragment-major copies (m16n8k16 layouts)
__device__ __half g_hfh[MBLK16 * 16 * 256];  // A fragments
__device__ __half g_Wfh[10 * WELEM];         // B fragments

__device__ __forceinline__ unsigned fenc(float f) {
    unsigned u = __float_as_uint(f);
    return (u & 0x80000000u) ? ~u : (u | 0x80000000u);
}
__device__ __forceinline__ float fdec(unsigned u) {
    u = (u & 0x80000000u) ? (u & 0x7FFFFFFFu) : ~u;
    return __uint_as_float(u);
}
#define ENC_NEG_INF 0x007FFFFFu

// A-fragment store for m16n8k16: element (m, k) of h.
__device__ __forceinline__ void store_frag_h(int m, int k, float v) {
    int blk = (m >> 4) * 16 + (k >> 4);
    int lane = (m & 7) * 4 + ((k & 7) >> 1);
    int pos = ((m >> 3) & 1) * 2 + ((k >> 3) & 1) * 4 + (k & 1);
    g_hfh[blk * 256 + lane * 8 + pos] = __float2half(v);
}

#define CP16(dst, src) \
    asm volatile("cp.async.cg.shared.global [%0], [%1], 16;" \
                 :: "r"(dst), "l"(src) : "memory")

__device__ __forceinline__ uint32_t smem_u32(const void* p) {
    uint32_t a;
    asm("{ .reg .u64 t; cvta.to.shared.u64 t, %1; cvt.u32.u64 %0, t; }"
        : "=r"(a) : "l"(p));
    return a;
}

__device__ __forceinline__ void mma_f16(float* c, const uint4& a, const uint2& b) {
    asm volatile(
        "mma.sync.aligned.m16n8k16.row.col.f32.f16.f16.f32 "
        "{%0,%1,%2,%3}, {%4,%5,%6,%7}, {%8,%9}, {%0,%1,%2,%3};\n"
        : "+f"(c[0]), "+f"(c[1]), "+f"(c[2]), "+f"(c[3])
        : "r"(a.x), "r"(a.y), "r"(a.z), "r"(a.w), "r"(b.x), "r"(b.y));
}

// ---------------- pre: self-loop attr + degree ---------------------------------
__global__ void k_init_pre() {
    int i = blockIdx.x * blockDim.x + threadIdx.x;
    if (i < NN * BONDD) g_loopsum[i] = 0.f;
    if (i < NN) { g_deg[i] = 0.f; g_degi[i] = 0; }
}

__global__ void k_degattr(const int* __restrict__ dst, const float* __restrict__ ea) {
    int j = blockIdx.x * blockDim.x + threadIdx.x;
    if (j >= EE * BONDD) return;
    int e = j / BONDD, b = j - e * BONDD;
    int d = dst[e];
    atomicAdd(&g_loopsum[d * BONDD + b], ea[j]);
    if (b == 0) { atomicAdd(&g_deg[d], 1.f); atomicAdd(&g_degi[d], 1); }
}

__global__ void k_loopdiv() {
    int j = blockIdx.x * blockDim.x + threadIdx.x;
    if (j >= NN * BONDD) return;
    int n = j / BONDD;
    g_loop[j] = g_loopsum[j] / fmaxf(g_deg[n], 1.f);
}

// unified edge-attr table: real edges then self loops
__global__ void k_buildea(const float* __restrict__ edge_attr) {
    int j = blockIdx.x * blockDim.x + threadIdx.x;
    if (j >= EAA * BONDD) return;
    g_ea[j] = (j < EE * BONDD) ? edge_attr[j] : g_loop[j - EE * BONDD];
}

// ---------------- CSR: scan + fill --------------------------------------------
__global__ void k_scan() {
    __shared__ int sums[1024];
    int t = threadIdx.x;
    int base = t * 8;
    int loc[8];
    int s = 0;
    #pragma unroll
    for (int i = 0; i < 8; i++) {
        loc[i] = s;
        int idx = base + i;
        s += (idx < NN) ? g_degi[idx] : 0;
    }
    sums[t] = s;
    __syncthreads();
    for (int off = 1; off < 1024; off <<= 1) {
        int v = (t >= off) ? sums[t - off] : 0;
        __syncthreads();
        sums[t] += v;
        __syncthreads();
    }
    int pre = (t == 0) ? 0 : sums[t - 1];
    #pragma unroll
    for (int i = 0; i < 8; i++) {
        int idx = base + i;
        if (idx < NN) { g_csroff[idx] = pre + loc[i]; g_cur[idx] = pre + loc[i]; }
    }
    if (t == 0) g_csroff[NN] = EE;
}

__global__ void k_fill(const int* __restrict__ dst) {
    int e = blockIdx.x * blockDim.x + threadIdx.x;
    if (e >= EE) return;
    int d = dst[e];
    int pos = atomicAdd(&g_cur[d], 1);
    g_csre[pos] = e;
}

// ---------------- W -> fp16 B-fragment-major layout (m16n8k16) -----------------
__global__ void k_prepW(const float* __restrict__ Wl, const float* __restrict__ Wr) {
    int z = blockIdx.y;  // 0..9 = l*2+which
    const float* W = ((z & 1) ? Wr : Wl) + (size_t)(z >> 1) * HD * HHD;
    int idx = blockIdx.x * 256 + threadIdx.x;
    int k = idx >> 11;
    int n = idx & 2047;
    int blk = (n >> 3) * 16 + (k >> 4);
    int lane = (n & 7) * 4 + ((k & 7) >> 1);
    int pos = ((k >> 3) & 1) * 2 + (k & 1);
    g_Wfh[(size_t)z * WELEM + blk * 128 + lane * 4 + pos] = __float2half(W[idx]);
}

// ---------------- atom embedding: relu(LN(x @ W + b)) -------------------------
__global__ void k_embed(const float* __restrict__ x, const float* __restrict__ W,
                        const float* __restrict__ b, const float* __restrict__ g,
                        const float* __restrict__ be) {
    int n = blockIdx.x, tid = threadIdx.x;
    __shared__ float sx[ATOMD];
    __shared__ float rs[8], rq[8];
    if (tid < ATOMD) sx[tid] = x[n * ATOMD + tid];
    __syncthreads();
    float acc = b[tid];
    for (int k = 0; k < ATOMD; k++) acc += sx[k] * W[k * HD + tid];
    float a = acc, q = acc * acc;
    #pragma unroll
    for (int o = 16; o; o >>= 1) {
        a += __shfl_xor_sync(~0u, a, o);
        q += __shfl_xor_sync(~0u, q, o);
    }
    int lane = tid & 31, w = tid >> 5;
    if (!lane) { rs[w] = a; rq[w] = q; }
    __syncthreads();
    float sum = 0.f, sq = 0.f;
    #pragma unroll
    for (int i = 0; i < 8; i++) { sum += rs[i]; sq += rq[i]; }
    float mean = sum * (1.f / HD);
    float var = sq * (1.f / HD) - mean * mean;
    float y = (acc - mean) * rsqrtf(var + 1e-5f) * g[tid] + be[tid];
    y = fmaxf(y, 0.f);
    g_h[n * HD + tid] = y;
    store_frag_h(n, tid, y);
}

// ---------------- fp16 mma GEMM: C = h[8000,256] @ W[256,2048] (fp16 out) -----
// 128x128 CTA tile, 8 warps (4m x 2n), warp tile 32x64, k-tile 32, 2-stage.
__global__ void __launch_bounds__(256, 2) k_gemm_mma(int l) {
    extern __shared__ __half smh[];
    const int t = threadIdx.x;
    const int warp = t >> 5, lane = t & 31;
    const int wm = warp & 3, wn = warp >> 2;
    const int gr = lane >> 2, tg = lane & 3;
    const int m0 = blockIdx.y * 128, n0 = blockIdx.x * 128;
    const int wi = l * 2 + blockIdx.z;
    __half* C = blockIdx.z ? g_xr : g_xl;
    const __half* Ab = g_hfh + (size_t)(m0 >> 4) * 16 * 256;
    const __half* Bb = g_Wfh + (size_t)wi * WELEM + (size_t)(n0 >> 3) * 16 * 128;
    const uint32_t sbase = smem_u32(smh);

    float c[2][8][4];
    #pragma unroll
    for (int i = 0; i < 2; i++)
        #pragma unroll
        for (int j = 0; j < 8; j++)
            #pragma unroll
            for (int k = 0; k < 4; k++) c[i][j][k] = 0.f;

    // stage s: A at halfs [s*4096, +4096), B at halfs [8192 + s*4096, +4096)
    #define PREFETCH(kt, s) do { \
        _Pragma("unroll") \
        for (int p = 0; p < 2; p++) { \
            int u = p * 256 + t;              /* 0..511 A cp16s */ \
            int lb = u >> 5, q = u & 31;      /* local block, 16B unit */ \
            int i = lb >> 1, kb = lb & 1; \
            const __half* srcA = Ab + ((size_t)i * 16 + (kt) * 2 + kb) * 256 + q * 8; \
            CP16(sbase + ((s) * 4096 + lb * 256 + q * 8) * 2, srcA); \
        } \
        _Pragma("unroll") \
        for (int p = 0; p < 2; p++) { \
            int u = p * 256 + t;              /* 0..511 B cp16s */ \
            int lb = u >> 4, q = u & 15; \
            int j = lb >> 1, kb = lb & 1; \
            const __half* srcB = Bb + ((size_t)j * 16 + (kt) * 2 + kb) * 128 + q * 8; \
            CP16(sbase + (8192 + (s) * 4096 + lb * 128 + q * 8) * 2, srcB); \
        } \
        asm volatile("cp.async.commit_group;" ::: "memory"); \
    } while (0)

    PREFETCH(0, 0);
    for (int kt = 0; kt < 8; kt++) {
        int s = kt & 1;
        if (kt < 7) {
            PREFETCH(kt + 1, s ^ 1);
            asm volatile("cp.async.wait_group 1;" ::: "memory");
        } else {
            asm volatile("cp.async.wait_group 0;" ::: "memory");
        }
        __syncthreads();
        const __half* A = smh + s * 4096;
        const __half* B = smh + 8192 + s * 4096;
        #pragma unroll
        for (int ks = 0; ks < 2; ks++) {
            uint4 a[2];
            a[0] = *(const uint4*)&A[((wm * 2 + 0) * 2 + ks) * 256 + lane * 8];
            a[1] = *(const uint4*)&A[((wm * 2 + 1) * 2 + ks) * 256 + lane * 8];
            uint2 b[8];
            #pragma unroll
            for (int jn = 0; jn < 8; jn++)
                b[jn] = *(const uint2*)&B[((wn * 8 + jn) * 2 + ks) * 128 + lane * 4];
            #pragma unroll
            for (int jn = 0; jn < 8; jn++)
                #pragma unroll
                for (int im = 0; im < 2; im++)
                    mma_f16(c[im][jn], a[im], b[jn]);
        }
        __syncthreads();
    }
    #undef PREFETCH

    #pragma unroll
    for (int im = 0; im < 2; im++) {
        #pragma unroll
        for (int jn = 0; jn < 8; jn++) {
            int row = m0 + wm * 32 + im * 16 + gr;
            int col = n0 + wn * 64 + jn * 8 + tg * 2;
            if (row < NN)
                *(__half2*)&C[(size_t)row * HHD + col] =
                    __floats2half2_rn(c[im][jn][0], c[im][jn][1]);
            if (row + 8 < NN)
                *(__half2*)&C[(size_t)(row + 8) * HHD + col] =
                    __floats2half2_rn(c[im][jn][2], c[im][jn][3]);
        }
    }
}

// ---------------- fused score: leaky(xl[s]+xr[d]+ea@We) . att -----------------
// grid (EAA/32, NHEADS); block = 32 edges x 1 head; We in registers.
__global__ void __launch_bounds__(256) k_score2(
    const int* __restrict__ src, const int* __restrict__ dst,
    const float* __restrict__ We_l, const float* __restrict__ att_l) {
    __shared__ float sea[32][BONDD];
    __shared__ int ssrc[32], sdst[32];
    __shared__ float prod[32][257];
    int e0 = blockIdx.x * 32, h = blockIdx.y, t = threadIdx.x;
    int col = h * HD + t;

    for (int j = t; j < 32 * BONDD; j += 256)
        sea[j / BONDD][j % BONDD] = g_ea[e0 * BONDD + j];
    if (t < 32) {
        int e = e0 + t;
        ssrc[t] = (e < EE) ? src[e] : (e - EE);
        sdst[t] = (e < EE) ? dst[e] : (e - EE);
    }
    float w[BONDD];
    #pragma unroll
    for (int b = 0; b < BONDD; b++) w[b] = We_l[b * HHD + col];
    float av = att_l[col];
    __syncthreads();

    #pragma unroll 4
    for (int e = 0; e < 32; e++) {
        float ee = 0.f;
        #pragma unroll
        for (int b = 0; b < BONDD; b++) ee = fmaf(sea[e][b], w[b], ee);
        float v = __half2float(g_xl[(size_t)ssrc[e] * HHD + col]) +
                  __half2float(g_xr[(size_t)sdst[e] * HHD + col]) + ee;
        v = v > 0.f ? v : 0.2f * v;
        prod[e][t] = v * av;
    }
    __syncthreads();

    // reduce 256 cols per edge: 8 threads per edge, stride-8 reads
    int e = t >> 3, sub = t & 7;
    float acc = 0.f;
    #pragma unroll
    for (int i = 0; i < 32; i++) acc += prod[e][sub + 8 * i];
    #pragma unroll
    for (int o = 4; o; o >>= 1) acc += __shfl_xor_sync(~0u, acc, o);
    if (sub == 0) g_score[(e0 + e) * NHEADS + h] = acc;
}

// ---------------- fused message: local softmax + gather + residual + LN -------
__global__ void __launch_bounds__(256) k_msgln(
    const int* __restrict__ src, const float* __restrict__ bias_l,
    const float* __restrict__ lng, const float* __restrict__ lnb) {
    int d = blockIdx.x, t = threadIdx.x;
    __shared__ int s_src[MAXD];
    __shared__ float s_alpha[NHEADS][MAXD];
    __shared__ float rs[8], rq[8];

    int off = g_csroff[d];
    int deg = g_csroff[d + 1] - off;
    if (deg > MAXD - 1) deg = MAXD - 1;
    int ne = deg + 1;                     // + self loop

    for (int i = t; i < deg; i += 256) s_src[i] = src[g_csre[off + i]];
    if (t == 0) s_src[deg] = d;
    for (int j = t; j < ne * NHEADS; j += 256) {
        int i = j >> 3, h = j & 7;
        int e = (i < deg) ? g_csre[off + i] : (EE + d);
        s_alpha[h][i] = g_score[e * NHEADS + h];
    }
    __syncthreads();

    if (t < NHEADS) {
        float m = -3.4e38f;
        for (int i = 0; i < ne; i++) m = fmaxf(m, s_alpha[t][i]);
        float sum = 0.f;
        for (int i = 0; i < ne; i++) {
            float ex = expf(s_alpha[t][i] - m);
            s_alpha[t][i] = ex;
            sum += ex;
        }
        float inv = 1.f / sum;
        for (int i = 0; i < ne; i++) s_alpha[t][i] *= inv;
    }
    __syncthreads();

    float acc = 0.f;
    for (int i = 0; i < ne; i++) {
        const __half* xlr = g_xl + (size_t)s_src[i] * HHD;
        #pragma unroll
        for (int h = 0; h < NHEADS; h++)
            acc = fmaf(__half2float(xlr[h * HD + t]), s_alpha[h][i], acc);
    }

    float v = 0.125f * acc + bias_l[t] + g_h[d * HD + t];
    float a = v, q = v * v;
    #pragma unroll
    for (int o = 16; o; o >>= 1) {
        a += __shfl_xor_sync(~0u, a, o);
        q += __shfl_xor_sync(~0u, q, o);
    }
    int lane = t & 31, w = t >> 5;
    if (!lane) { rs[w] = a; rq[w] = q; }
    __syncthreads();
    float sum = 0.f, sq = 0.f;
    #pragma unroll
    for (int i = 0; i < 8; i++) { sum += rs[i]; sq += rq[i]; }
    float mean = sum * (1.f / HD);
    float var = sq * (1.f / HD) - mean * mean;
    float y = (v - mean) * rsqrtf(var + 1e-5f) * lng[t] + lnb[t];
    g_h[d * HD + t] = y;
    store_frag_h(d, t, y);
}

// ---------------- readout -----------------------------------------------------
__global__ void k_initread(float* __restrict__ out) {
    int i = blockIdx.x * blockDim.x + threadIdx.x;
    if (i < BB * HD) out[i] = 0.f;
    if (i < BB) { g_gm[i] = ENC_NEG_INF; g_gs[i] = 0.f; }
}

__global__ void k_gate(const float* __restrict__ W1, const float* __restrict__ b1,
                       const float* __restrict__ W2, const float* __restrict__ b2,
                       const int* __restrict__ batch) {
    int n = blockIdx.x, tid = threadIdx.x;
    __shared__ float sh[HD];
    __shared__ float rs[4];
    sh[tid] = g_h[n * HD + tid];
    sh[tid + 128] = g_h[n * HD + tid + 128];
    __syncthreads();
    float acc = b1[tid];
    for (int k = 0; k < HD; k++) acc += sh[k] * W1[k * 128 + tid];
    float part = fmaxf(acc, 0.f) * W2[tid];
    #pragma unroll
    for (int o = 16; o; o >>= 1) part += __shfl_xor_sync(~0u, part, o);
    int lane = tid & 31, w = tid >> 5;
    if (!lane) rs[w] = part;
    __syncthreads();
    if (tid == 0) {
        float gate = rs[0] + rs[1] + rs[2] + rs[3] + b2[0];
        g_gate[n] = gate;
        atomicMax(&g_gm[batch[n]], fenc(gate));
    }
}

__global__ void k_gexp(const int* __restrict__ batch) {
    int n = blockIdx.x * blockDim.x + threadIdx.x;
    if (n >= NN) return;
    int b = batch[n];
    float ge = expf(g_gate[n] - fdec(g_gm[b]));
    g_ge[n] = ge;
    atomicAdd(&g_gs[b], ge);
}

__global__ void k_readout(const int* __restrict__ batch, float* __restrict__ out) {
    int n = blockIdx.x, tid = threadIdx.x;
    int b = batch[n];
    float w = g_ge[n] / fmaxf(g_gs[b], 1e-16f);
    atomicAdd(&out[b * HD + tid], w * g_h[n * HD + tid]);
}

// ---------------- launcher ----------------------------------------------------
extern "C" void kernel_launch(void* const* d_in, const int* in_sizes, int n_in,
                              void* d_out, int out_size) {
    const float* x         = (const float*)d_in[0];
    const float* edge_attr = (const float*)d_in[1];
    const float* emb_W     = (const float*)d_in[2];
    const float* emb_b     = (const float*)d_in[3];
    const float* emb_g     = (const float*)d_in[4];
    const float* emb_beta  = (const float*)d_in[5];
    const float* Wl        = (const float*)d_in[6];
    const float* Wr        = (const float*)d_in[7];
    const float* We        = (const float*)d_in[8];
    const float* att       = (const float*)d_in[9];
    const float* bias      = (const float*)d_in[10];
    const float* ln_g      = (const float*)d_in[11];
    const float* ln_b      = (const float*)d_in[12];
    const float* g1W       = (const float*)d_in[13];
    const float* g1b       = (const float*)d_in[14];
    const float* g2W       = (const float*)d_in[15];
    const float* g2b       = (const float*)d_in[16];
    const int* edge_index  = (const int*)d_in[17];
    const int* batch       = (const int*)d_in[18];
    const int* src = edge_index;
    const int* dst = edge_index + EE;
    float* out = (float*)d_out;

    cudaFuncSetAttribute(k_gemm_mma, cudaFuncAttributeMaxDynamicSharedMemorySize, 32768);

    k_init_pre<<<(NN * BONDD + 255) / 256, 256>>>();
    k_degattr<<<(EE * BONDD + 255) / 256, 256>>>(dst, edge_attr);
    k_loopdiv<<<(NN * BONDD + 255) / 256, 256>>>();
    k_buildea<<<(EAA * BONDD + 255) / 256, 256>>>(edge_attr);
    k_scan<<<1, 1024>>>();
    k_fill<<<(EE + 255) / 256, 256>>>(dst);
    k_prepW<<<dim3((HD * HHD) / 256, 10), 256>>>(Wl, Wr);
    k_embed<<<NN, HD>>>(x, emb_W, emb_b, emb_g, emb_beta);

    dim3 gg(HHD / 128, (NN + 127) / 128, 2);
    dim3 gs(EAA / 32, NHEADS);
    for (int l = 0; l < NLAYERS; l++) {
        k_gemm_mma<<<gg, 256, 32768>>>(l);
        k_score2<<<gs, 256>>>(src, dst,
                              We + (size_t)l * BONDD * HHD,
                              att + (size_t)l * NHEADS * HD);
        k_msgln<<<NN, HD>>>(src, bias + l * HD, ln_g + l * HD, ln_b + l * HD);
    }

    k_initread<<<(BB * HD + 255) / 256, 256>>>(out);
    k_gate<<<NN, 128>>>(g1W, g1b, g2W, g2b, batch);
    k_gexp<<<(NN + 255) / 256, 256>>>(batch);
    k_readout<<<NN, HD>>>(batch, out);
}

// round 17
// speedup vs baseline: 2.8061x; 1.0402x over previous
#include <cuda_runtime.h>
#include <cuda_fp16.h>
#include <math.h>
#include <stdint.h>

#define NN 8000
#define EE 24000
#define EAA 32000
#define BB 256
#define ATOMD 133
#define BONDD 14
#define HD 256
#define NHEADS 8
#define HHD 2048
#define NLAYERS 5
#define MAXD 64

#define MBLK16 504               // padded m-blocks of 16 (ceil(8064/16))
#define WELEM 524288             // halfs per weight matrix

// ---------------- scratch (device globals; no allocation allowed) -------------
__device__ float g_h[NN * HD];
__device__ __half g_xl[NN * HHD];
__device__ __half g_xr[NN * HHD];
__device__ float g_score[EAA * NHEADS];     // raw scores
__device__ float g_deg[NN];
__device__ float g_loopsum[NN * BONDD];
__device__ float g_loop[NN * BONDD];
__device__ float g_ea[EAA * BONDD];         // unified edge attrs (incl. self loops)
__device__ float g_gate[NN];
__device__ float g_ge[NN];
__device__ unsigned g_gm[BB];
__device__ float g_gs[BB];
// CSR by destination
__device__ int g_degi[NN];
__device__ int g_csroff[NN + 1];
__device__ int g_cur[NN];
__device__ int g_csre[EE];
// fp16 mma-fragment-major copies (m16n8k16 layouts)
__device__ __half g_hfh[MBLK16 * 16 * 256];  // A fragments
__device__ __half g_Wfh[10 * WELEM];         // B fragments

__device__ __forceinline__ unsigned fenc(float f) {
    unsigned u = __float_as_uint(f);
    return (u & 0x80000000u) ? ~u : (u | 0x80000000u);
}
__device__ __forceinline__ float fdec(unsigned u) {
    u = (u & 0x80000000u) ? (u & 0x7FFFFFFFu) : ~u;
    return __uint_as_float(u);
}
#define ENC_NEG_INF 0x007FFFFFu

// A-fragment store for m16n8k16: element (m, k) of h.
__device__ __forceinline__ void store_frag_h(int m, int k, float v) {
    int blk = (m >> 4) * 16 + (k >> 4);
    int lane = (m & 7) * 4 + ((k & 7) >> 1);
    int pos = ((m >> 3) & 1) * 2 + ((k >> 3) & 1) * 4 + (k & 1);
    g_hfh[blk * 256 + lane * 8 + pos] = __float2half(v);
}

#define CP16(dst, src) \
    asm volatile("cp.async.cg.shared.global [%0], [%1], 16;" \
                 :: "r"(dst), "l"(src) : "memory")

__device__ __forceinline__ uint32_t smem_u32(const void* p) {
    uint32_t a;
    asm("{ .reg .u64 t; cvta.to.shared.u64 t, %1; cvt.u32.u64 %0, t; }"
        : "=r"(a) : "l"(p));
    return a;
}

__device__ __forceinline__ void mma_f16(float* c, const uint4& a, const uint2& b) {
    asm volatile(
        "mma.sync.aligned.m16n8k16.row.col.f32.f16.f16.f32 "
        "{%0,%1,%2,%3}, {%4,%5,%6,%7}, {%8,%9}, {%0,%1,%2,%3};\n"
        : "+f"(c[0]), "+f"(c[1]), "+f"(c[2]), "+f"(c[3])
        : "r"(a.x), "r"(a.y), "r"(a.z), "r"(a.w), "r"(b.x), "r"(b.y));
}

// ---------------- pre: self-loop attr + degree ---------------------------------
__global__ void k_init_pre() {
    int i = blockIdx.x * blockDim.x + threadIdx.x;
    if (i < NN * BONDD) g_loopsum[i] = 0.f;
    if (i < NN) { g_deg[i] = 0.f; g_degi[i] = 0; }
}

__global__ void k_degattr(const int* __restrict__ dst, const float* __restrict__ ea) {
    int j = blockIdx.x * blockDim.x + threadIdx.x;
    if (j >= EE * BONDD) return;
    int e = j / BONDD, b = j - e * BONDD;
    int d = dst[e];
    atomicAdd(&g_loopsum[d * BONDD + b], ea[j]);
    if (b == 0) { atomicAdd(&g_deg[d], 1.f); atomicAdd(&g_degi[d], 1); }
}

__global__ void k_loopdiv() {
    int j = blockIdx.x * blockDim.x + threadIdx.x;
    if (j >= NN * BONDD) return;
    int n = j / BONDD;
    g_loop[j] = g_loopsum[j] / fmaxf(g_deg[n], 1.f);
}

// unified edge-attr table: real edges then self loops
__global__ void k_buildea(const float* __restrict__ edge_attr) {
    int j = blockIdx.x * blockDim.x + threadIdx.x;
    if (j >= EAA * BONDD) return;
    g_ea[j] = (j < EE * BONDD) ? edge_attr[j] : g_loop[j - EE * BONDD];
}

// ---------------- CSR: scan + fill --------------------------------------------
__global__ void k_scan() {
    __shared__ int sums[1024];
    int t = threadIdx.x;
    int base = t * 8;
    int loc[8];
    int s = 0;
    #pragma unroll
    for (int i = 0; i < 8; i++) {
        loc[i] = s;
        int idx = base + i;
        s += (idx < NN) ? g_degi[idx] : 0;
    }
    sums[t] = s;
    __syncthreads();
    for (int off = 1; off < 1024; off <<= 1) {
        int v = (t >= off) ? sums[t - off] : 0;
        __syncthreads();
        sums[t] += v;
        __syncthreads();
    }
    int pre = (t == 0) ? 0 : sums[t - 1];
    #pragma unroll
    for (int i = 0; i < 8; i++) {
        int idx = base + i;
        if (idx < NN) { g_csroff[idx] = pre + loc[i]; g_cur[idx] = pre + loc[i]; }
    }
    if (t == 0) g_csroff[NN] = EE;
}

__global__ void k_fill(const int* __restrict__ dst) {
    int e = blockIdx.x * blockDim.x + threadIdx.x;
    if (e >= EE) return;
    int d = dst[e];
    int pos = atomicAdd(&g_cur[d], 1);
    g_csre[pos] = e;
}

// ---------------- W -> fp16 B-fragment-major layout (k-pair half2 stores) ------
__global__ void k_prepW(const float* __restrict__ Wl, const float* __restrict__ Wr) {
    int z = blockIdx.y;  // 0..9 = l*2+which
    const float* W = ((z & 1) ? Wr : Wl) + (size_t)(z >> 1) * HD * HHD;
    int idx = blockIdx.x * 256 + threadIdx.x;   // over (HD/2)*HHD
    int kk = idx >> 11;          // k-pair index 0..127
    int n = idx & 2047;
    int k = kk * 2;
    float v0 = W[(size_t)k * HHD + n];
    float v1 = W[(size_t)(k + 1) * HHD + n];
    int blk = (n >> 3) * 16 + (k >> 4);
    int lane = (n & 7) * 4 + ((k & 7) >> 1);
    int p = (k >> 3) & 1;
    *(__half2*)&g_Wfh[(size_t)z * WELEM + blk * 128 + lane * 4 + p * 2] =
        __floats2half2_rn(v0, v1);
}

// ---------------- atom embedding: relu(LN(x @ W + b)) -------------------------
__global__ void k_embed(const float* __restrict__ x, const float* __restrict__ W,
                        const float* __restrict__ b, const float* __restrict__ g,
                        const float* __restrict__ be) {
    int n = blockIdx.x, tid = threadIdx.x;
    __shared__ float sx[ATOMD];
    __shared__ float rs[8], rq[8];
    if (tid < ATOMD) sx[tid] = x[n * ATOMD + tid];
    __syncthreads();
    float acc = b[tid];
    for (int k = 0; k < ATOMD; k++) acc += sx[k] * W[k * HD + tid];
    float a = acc, q = acc * acc;
    #pragma unroll
    for (int o = 16; o; o >>= 1) {
        a += __shfl_xor_sync(~0u, a, o);
        q += __shfl_xor_sync(~0u, q, o);
    }
    int lane = tid & 31, w = tid >> 5;
    if (!lane) { rs[w] = a; rq[w] = q; }
    __syncthreads();
    float sum = 0.f, sq = 0.f;
    #pragma unroll
    for (int i = 0; i < 8; i++) { sum += rs[i]; sq += rq[i]; }
    float mean = sum * (1.f / HD);
    float var = sq * (1.f / HD) - mean * mean;
    float y = (acc - mean) * rsqrtf(var + 1e-5f) * g[tid] + be[tid];
    y = fmaxf(y, 0.f);
    g_h[n * HD + tid] = y;
    store_frag_h(n, tid, y);
}

// ---------------- fp16 mma GEMM: 3-stage cp.async, 1 barrier per k-tile -------
// 128x128 CTA tile, 8 warps (4m x 2n), warp tile 32x64, k-tile 32.
__global__ void __launch_bounds__(256, 2) k_gemm_mma(int l) {
    extern __shared__ __half smh[];
    const int t = threadIdx.x;
    const int warp = t >> 5, lane = t & 31;
    const int wm = warp & 3, wn = warp >> 2;
    const int gr = lane >> 2, tg = lane & 3;
    const int m0 = blockIdx.y * 128, n0 = blockIdx.x * 128;
    const int wi = l * 2 + blockIdx.z;
    __half* C = blockIdx.z ? g_xr : g_xl;
    const __half* Ab = g_hfh + (size_t)(m0 >> 4) * 16 * 256;
    const __half* Bb = g_Wfh + (size_t)wi * WELEM + (size_t)(n0 >> 3) * 16 * 128;
    const uint32_t sbase = smem_u32(smh);

    float c[2][8][4];
    #pragma unroll
    for (int i = 0; i < 2; i++)
        #pragma unroll
        for (int j = 0; j < 8; j++)
            #pragma unroll
            for (int k = 0; k < 4; k++) c[i][j][k] = 0.f;

    // stage s (0..2): A at halfs [s*4096), B at halfs [12288 + s*4096)
    #define PREFETCH(kt, s) do { \
        _Pragma("unroll") \
        for (int p = 0; p < 2; p++) { \
            int u = p * 256 + t; \
            int lb = u >> 5, q = u & 31; \
            int i = lb >> 1, kb = lb & 1; \
            const __half* srcA = Ab + ((size_t)i * 16 + (kt) * 2 + kb) * 256 + q * 8; \
            CP16(sbase + ((s) * 4096 + lb * 256 + q * 8) * 2, srcA); \
        } \
        _Pragma("unroll") \
        for (int p = 0; p < 2; p++) { \
            int u = p * 256 + t; \
            int lb = u >> 4, q = u & 15; \
            int j = lb >> 1, kb = lb & 1; \
            const __half* srcB = Bb + ((size_t)j * 16 + (kt) * 2 + kb) * 128 + q * 8; \
            CP16(sbase + (12288 + (s) * 4096 + lb * 128 + q * 8) * 2, srcB); \
        } \
        asm volatile("cp.async.commit_group;" ::: "memory"); \
    } while (0)

    PREFETCH(0, 0);
    PREFETCH(1, 1);
    #pragma unroll
    for (int kt = 0; kt < 8; kt++) {
        int s = kt % 3;
        if (kt < 7) {
            asm volatile("cp.async.wait_group 1;" ::: "memory");
        } else {
            asm volatile("cp.async.wait_group 0;" ::: "memory");
        }
        __syncthreads();
        if (kt < 6) PREFETCH(kt + 2, (kt + 2) % 3);
        const __half* A = smh + s * 4096;
        const __half* B = smh + 12288 + s * 4096;
        #pragma unroll
        for (int ks = 0; ks < 2; ks++) {
            uint4 a[2];
            a[0] = *(const uint4*)&A[((wm * 2 + 0) * 2 + ks) * 256 + lane * 8];
            a[1] = *(const uint4*)&A[((wm * 2 + 1) * 2 + ks) * 256 + lane * 8];
            uint2 b[8];
            #pragma unroll
            for (int jn = 0; jn < 8; jn++)
                b[jn] = *(const uint2*)&B[((wn * 8 + jn) * 2 + ks) * 128 + lane * 4];
            #pragma unroll
            for (int jn = 0; jn < 8; jn++)
                #pragma unroll
                for (int im = 0; im < 2; im++)
                    mma_f16(c[im][jn], a[im], b[jn]);
        }
    }
    #undef PREFETCH

    #pragma unroll
    for (int im = 0; im < 2; im++) {
        #pragma unroll
        for (int jn = 0; jn < 8; jn++) {
            int row = m0 + wm * 32 + im * 16 + gr;
            int col = n0 + wn * 64 + jn * 8 + tg * 2;
            if (row < NN)
                *(__half2*)&C[(size_t)row * HHD + col] =
                    __floats2half2_rn(c[im][jn][0], c[im][jn][1]);
            if (row + 8 < NN)
                *(__half2*)&C[(size_t)(row + 8) * HHD + col] =
                    __floats2half2_rn(c[im][jn][2], c[im][jn][3]);
        }
    }
}

// ---------------- fused score: leaky(xl[s]+xr[d]+ea@We) . att -----------------
// grid (EAA/32, NHEADS); block = 32 edges x 1 head; We in registers.
__global__ void __launch_bounds__(256) k_score2(
    const int* __restrict__ src, const int* __restrict__ dst,
    const float* __restrict__ We_l, const float* __restrict__ att_l) {
    __shared__ float sea[32][BONDD];
    __shared__ int ssrc[32], sdst[32];
    __shared__ float prod[32][257];
    int e0 = blockIdx.x * 32, h = blockIdx.y, t = threadIdx.x;
    int col = h * HD + t;

    for (int j = t; j < 32 * BONDD; j += 256)
        sea[j / BONDD][j % BONDD] = g_ea[e0 * BONDD + j];
    if (t < 32) {
        int e = e0 + t;
        ssrc[t] = (e < EE) ? src[e] : (e - EE);
        sdst[t] = (e < EE) ? dst[e] : (e - EE);
    }
    float w[BONDD];
    #pragma unroll
    for (int b = 0; b < BONDD; b++) w[b] = We_l[b * HHD + col];
    float av = att_l[col];
    __syncthreads();

    #pragma unroll 4
    for (int e = 0; e < 32; e++) {
        float ee = 0.f;
        #pragma unroll
        for (int b = 0; b < BONDD; b++) ee = fmaf(sea[e][b], w[b], ee);
        float v = __half2float(g_xl[(size_t)ssrc[e] * HHD + col]) +
                  __half2float(g_xr[(size_t)sdst[e] * HHD + col]) + ee;
        v = v > 0.f ? v : 0.2f * v;
        prod[e][t] = v * av;
    }
    __syncthreads();

    // reduce 256 cols per edge: 8 threads per edge, stride-8 reads
    int e = t >> 3, sub = t & 7;
    float acc = 0.f;
    #pragma unroll
    for (int i = 0; i < 32; i++) acc += prod[e][sub + 8 * i];
    #pragma unroll
    for (int o = 4; o; o >>= 1) acc += __shfl_xor_sync(~0u, acc, o);
    if (sub == 0) g_score[(e0 + e) * NHEADS + h] = acc;
}

// ---------------- fused message: local softmax + gather + residual + LN -------
__global__ void __launch_bounds__(256) k_msgln(
    const int* __restrict__ src, const float* __restrict__ bias_l,
    const float* __restrict__ lng, const float* __restrict__ lnb) {
    int d = blockIdx.x, t = threadIdx.x;
    __shared__ int s_src[MAXD];
    __shared__ float s_alpha[NHEADS][MAXD];
    __shared__ float rs[8], rq[8];

    int off = g_csroff[d];
    int deg = g_csroff[d + 1] - off;
    if (deg > MAXD - 1) deg = MAXD - 1;
    int ne = deg + 1;                     // + self loop

    for (int i = t; i < deg; i += 256) s_src[i] = src[g_csre[off + i]];
    if (t == 0) s_src[deg] = d;
    for (int j = t; j < ne * NHEADS; j += 256) {
        int i = j >> 3, h = j & 7;
        int e = (i < deg) ? g_csre[off + i] : (EE + d);
        s_alpha[h][i] = g_score[e * NHEADS + h];
    }
    __syncthreads();

    if (t < NHEADS) {
        float m = -3.4e38f;
        for (int i = 0; i < ne; i++) m = fmaxf(m, s_alpha[t][i]);
        float sum = 0.f;
        for (int i = 0; i < ne; i++) {
            float ex = expf(s_alpha[t][i] - m);
            s_alpha[t][i] = ex;
            sum += ex;
        }
        float inv = 1.f / sum;
        for (int i = 0; i < ne; i++) s_alpha[t][i] *= inv;
    }
    __syncthreads();

    float acc = 0.f;
    for (int i = 0; i < ne; i++) {
        const __half* xlr = g_xl + (size_t)s_src[i] * HHD;
        #pragma unroll
        for (int h = 0; h < NHEADS; h++)
            acc = fmaf(__half2float(xlr[h * HD + t]), s_alpha[h][i], acc);
    }

    float v = 0.125f * acc + bias_l[t] + g_h[d * HD + t];
    float a = v, q = v * v;
    #pragma unroll
    for (int o = 16; o; o >>= 1) {
        a += __shfl_xor_sync(~0u, a, o);
        q += __shfl_xor_sync(~0u, q, o);
    }
    int lane = t & 31, w = t >> 5;
    if (!lane) { rs[w] = a; rq[w] = q; }
    __syncthreads();
    float sum = 0.f, sq = 0.f;
    #pragma unroll
    for (int i = 0; i < 8; i++) { sum += rs[i]; sq += rq[i]; }
    float mean = sum * (1.f / HD);
    float var = sq * (1.f / HD) - mean * mean;
    float y = (v - mean) * rsqrtf(var + 1e-5f) * lng[t] + lnb[t];
    g_h[d * HD + t] = y;
    store_frag_h(d, t, y);
}

// ---------------- readout -----------------------------------------------------
__global__ void k_initread(float* __restrict__ out) {
    int i = blockIdx.x * blockDim.x + threadIdx.x;
    if (i < BB * HD) out[i] = 0.f;
    if (i < BB) { g_gm[i] = ENC_NEG_INF; g_gs[i] = 0.f; }
}

__global__ void k_gate(const float* __restrict__ W1, const float* __restrict__ b1,
                       const float* __restrict__ W2, const float* __restrict__ b2,
                       const int* __restrict__ batch) {
    int n = blockIdx.x, tid = threadIdx.x;
    __shared__ float sh[HD];
    __shared__ float rs[4];
    sh[tid] = g_h[n * HD + tid];
    sh[tid + 128] = g_h[n * HD + tid + 128];
    __syncthreads();
    float acc = b1[tid];
    for (int k = 0; k < HD; k++) acc += sh[k] * W1[k * 128 + tid];
    float part = fmaxf(acc, 0.f) * W2[tid];
    #pragma unroll
    for (int o = 16; o; o >>= 1) part += __shfl_xor_sync(~0u, part, o);
    int lane = tid & 31, w = tid >> 5;
    if (!lane) rs[w] = part;
    __syncthreads();
    if (tid == 0) {
        float gate = rs[0] + rs[1] + rs[2] + rs[3] + b2[0];
        g_gate[n] = gate;
        atomicMax(&g_gm[batch[n]], fenc(gate));
    }
}

__global__ void k_gexp(const int* __restrict__ batch) {
    int n = blockIdx.x * blockDim.x + threadIdx.x;
    if (n >= NN) return;
    int b = batch[n];
    float ge = expf(g_gate[n] - fdec(g_gm[b]));
    g_ge[n] = ge;
    atomicAdd(&g_gs[b], ge);
}

__global__ void k_readout(const int* __restrict__ batch, float* __restrict__ out) {
    int n = blockIdx.x, tid = threadIdx.x;
    int b = batch[n];
    float w = g_ge[n] / fmaxf(g_gs[b], 1e-16f);
    atomicAdd(&out[b * HD + tid], w * g_h[n * HD + tid]);
}

// ---------------- launcher ----------------------------------------------------
extern "C" void kernel_launch(void* const* d_in, const int* in_sizes, int n_in,
                              void* d_out, int out_size) {
    const float* x         = (const float*)d_in[0];
    const float* edge_attr = (const float*)d_in[1];
    const float* emb_W     = (const float*)d_in[2];
    const float* emb_b     = (const float*)d_in[3];
    const float* emb_g     = (const float*)d_in[4];
    const float* emb_beta  = (const float*)d_in[5];
    const float* Wl        = (const float*)d_in[6];
    const float* Wr        = (const float*)d_in[7];
    const float* We        = (const float*)d_in[8];
    const float* att       = (const float*)d_in[9];
    const float* bias      = (const float*)d_in[10];
    const float* ln_g      = (const float*)d_in[11];
    const float* ln_b      = (const float*)d_in[12];
    const float* g1W       = (const float*)d_in[13];
    const float* g1b       = (const float*)d_in[14];
    const float* g2W       = (const float*)d_in[15];
    const float* g2b       = (const float*)d_in[16];
    const int* edge_index  = (const int*)d_in[17];
    const int* batch       = (const int*)d_in[18];
    const int* src = edge_index;
    const int* dst = edge_index + EE;
    float* out = (float*)d_out;

    cudaFuncSetAttribute(k_gemm_mma, cudaFuncAttributeMaxDynamicSharedMemorySize, 49152);

    k_init_pre<<<(NN * BONDD + 255) / 256, 256>>>();
    k_degattr<<<(EE * BONDD + 255) / 256, 256>>>(dst, edge_attr);
    k_loopdiv<<<(NN * BONDD + 255) / 256, 256>>>();
    k_buildea<<<(EAA * BONDD + 255) / 256, 256>>>(edge_attr);
    k_scan<<<1, 1024>>>();
    k_fill<<<(EE + 255) / 256, 256>>>(dst);
    k_prepW<<<dim3((HD / 2 * HHD) / 256, 10), 256>>>(Wl, Wr);
    k_embed<<<NN, HD>>>(x, emb_W, emb_b, emb_g, emb_beta);

    dim3 gg(HHD / 128, (NN + 127) / 128, 2);
    dim3 gs(EAA / 32, NHEADS);
    for (int l = 0; l < NLAYERS; l++) {
        k_gemm_mma<<<gg, 256, 49152>>>(l);
        k_score2<<<gs, 256>>>(src, dst,
                              We + (size_t)l * BONDD * HHD,
                              att + (size_t)l * NHEADS * HD);
        k_msgln<<<NN, HD>>>(src, bias + l * HD, ln_g + l * HD, ln_b + l * HD);
    }

    k_initread<<<(BB * HD + 255) / 256, 256>>>(out);
    k_gate<<<NN, 128>>>(g1W, g1b, g2W, g2b, batch);
    k_gexp<<<(NN + 255) / 256, 256>>>(batch);
    k_readout<<<NN, HD>>>(batch, out);
}